// round 12
// baseline (speedup 1.0000x reference)
#include <cuda_runtime.h>
#include <cuda_bf16.h>
#include <math.h>
#include <stdint.h>

// ---------------- problem constants -----------------------------------------
#define M_TOK 131072
#define C_DIM 384
#define HID_DIM 1536

// ---------------- scratch ----------------------------------------------------
__device__ float g_qkv[(size_t)M_TOK * 1152];
__device__ float g_y[(size_t)M_TOK * 384];
__device__ float g_x1[(size_t)M_TOK * 384];
__device__ __nv_bfloat16 g_ahi[(size_t)M_TOK * 1536];
__device__ __nv_bfloat16 g_alo[(size_t)M_TOK * 1536];
__device__ __nv_bfloat16 g_bhi[(size_t)M_TOK * 384];
__device__ __nv_bfloat16 g_blo[(size_t)M_TOK * 384];
__device__ __nv_bfloat16 g_whi[1769472];
__device__ __nv_bfloat16 g_wlo[1769472];
__device__ float g_tab[225 * 12];

#define WOFF_QKV 0
#define WOFF_PROJ 442368
#define WOFF_FC1 589824
#define WOFF_FC2 1179648

// ---------------- helpers -----------------------------------------------------
__device__ __forceinline__ uint32_t smem_u32(const void* p) {
    return (uint32_t)__cvta_generic_to_shared(p);
}

__device__ __forceinline__ void cp16(uint32_t dst, const void* src) {
    asm volatile("cp.async.cg.shared.global [%0], [%1], 16;" :: "r"(dst), "l"(src) : "memory");
}
#define CP_COMMIT() asm volatile("cp.async.commit_group;" ::: "memory")
#define CP_WAIT1() asm volatile("cp.async.wait_group 1;" ::: "memory")

__device__ __forceinline__ void mma_bf16(float* d, const uint32_t* a, const uint32_t* b) {
    asm volatile(
        "mma.sync.aligned.m16n8k16.row.col.f32.bf16.bf16.f32 "
        "{%0,%1,%2,%3}, {%4,%5,%6,%7}, {%8,%9}, {%0,%1,%2,%3};"
        : "+f"(d[0]), "+f"(d[1]), "+f"(d[2]), "+f"(d[3])
        : "r"(a[0]), "r"(a[1]), "r"(a[2]), "r"(a[3]), "r"(b[0]), "r"(b[1]));
}

__device__ __forceinline__ void split2(float v, __nv_bfloat16& h, __nv_bfloat16& l) {
    h = __float2bfloat16(v);
    l = __float2bfloat16(v - __bfloat162float(h));
}

__device__ __forceinline__ uint32_t packsplit_hi(float v0, float v1, uint32_t& lo) {
    __nv_bfloat16 h0, l0, h1, l1;
    split2(v0, h0, l0);
    split2(v1, h1, l1);
    __nv_bfloat162 hh = {h0, h1}, ll = {l0, l1};
    lo = *(uint32_t*)&ll;
    return *(uint32_t*)&hh;
}

__device__ __forceinline__ float fast_tanh(float z) {
    return 1.0f - 2.0f / (__expf(2.0f * z) + 1.0f);
}

// ---------------- index maps ------------------------------------------------
__device__ __forceinline__ int qkv_src_row(int r) {
    int b = r >> 12;
    int t = r & 4095;
    int win = t >> 6, p = t & 63;
    int wh = win >> 3, ww = win & 7;
    int i = p >> 3, j = p & 7;
    int h = (wh * 8 + i + 4) & 63;
    int w = (ww * 8 + j + 4) & 63;
    return (b << 12) + (h << 6) + w;
}

__device__ __forceinline__ int shift_label(int hs, int ws) {
    return ((hs < 56) ? 0 : ((hs < 60) ? 1 : 2)) * 3 +
           ((ws < 56) ? 0 : ((ws < 60) ? 1 : 2));
}

// ---------------- CPB table kernel ------------------------------------------
__device__ __forceinline__ float cpb_coord(int v) {
    float x = (float)v * (8.0f / 7.0f);
    float s = (x > 0.f) ? 1.f : ((x < 0.f) ? -1.f : 0.f);
    return s * log2f(fabsf(x) + 1.0f) * (1.0f / 3.0f);
}

__global__ void cpb_kernel(const float* __restrict__ w1, const float* __restrict__ b1,
                           const float* __restrict__ w2, float* __restrict__ tab) {
    int e = blockIdx.x * blockDim.x + threadIdx.x;
    if (e >= 225) return;
    int a = e / 15, b = e % 15;
    float in0 = cpb_coord(b - 7);
    float in1 = cpb_coord(a - 7);
    float out[12];
#pragma unroll
    for (int hh = 0; hh < 12; hh++) out[hh] = 0.f;
    for (int c = 0; c < 512; c++) {
        float hc = fmaf(in0, w1[c], fmaf(in1, w1[512 + c], b1[c]));
        hc = fmaxf(hc, 0.f);
#pragma unroll
        for (int hh = 0; hh < 12; hh++) out[hh] = fmaf(hc, w2[c * 12 + hh], out[hh]);
    }
#pragma unroll
    for (int hh = 0; hh < 12; hh++)
        tab[e * 12 + hh] = 16.0f / (1.0f + expf(-out[hh]));
}

// ---------------- weight prep ------------------------------------------------
__global__ void wprep_kernel(const float* __restrict__ W, __nv_bfloat16* __restrict__ hi,
                             __nv_bfloat16* __restrict__ lo, int K, int N) {
    int u = blockIdx.x * 256 + threadIdx.x;
    if (u >= K * N) return;
    int n = u / K, k = u % K;
    float v = W[(size_t)k * N + n];
    __nv_bfloat16 h, l;
    split2(v, h, l);
    hi[u] = h;
    lo[u] = l;
}

// ---------------- x gather + split -------------------------------------------
__global__ void xprep_kernel(const float* __restrict__ x, __nv_bfloat16* __restrict__ hi,
                             __nv_bfloat16* __restrict__ lo) {
    int u = blockIdx.x * 256 + threadIdx.x;
    int row = u / 96;
    int c4 = u % 96;
    int src = qkv_src_row(row);
    float4 v = *(const float4*)(x + (size_t)src * 384 + c4 * 4);
    uint2 hp, lp;
    hp.x = packsplit_hi(v.x, v.y, lp.x);
    hp.y = packsplit_hi(v.z, v.w, lp.y);
    *(uint2*)(hi + (size_t)row * 384 + c4 * 4) = hp;
    *(uint2*)(lo + (size_t)row * 384 + c4 * 4) = lp;
}

// ---------------- mma.sync split-bf16 GEMM (128x64 tile, 3 CTAs/SM) ----------
// C[M,N] = A[M,K] @ Wt[N,K]^T. 3-term split AhBh + AhBl + AlBh, fp32 accum.
// CTA tile 128(M) x 64(N); 8 warps of 32x32 (mt=2 m16 tiles, nt=4 n8 tiles).
// Smem: Ah(128xRS) Al(128xRS) Bh(64xRS) Bl(64xRS), RS=80 (perfect bank perm),
// double-buffered = 61440B -> 3 CTAs/SM; accs 32 regs -> <=85 regs/thread.
#define RS 80
#define MATB_A (128 * RS)        // 10240
#define MATB_B (64 * RS)         // 5120
#define STAGEB (2 * MATB_A + 2 * MATB_B)  // 30720
#define GEMM_SMEM (2 * STAGEB)   // 61440

template <int EPI>
__global__ __launch_bounds__(256, 3)
void gemm_mma(const __nv_bfloat16* __restrict__ Ahi, const __nv_bfloat16* __restrict__ Alo,
              const __nv_bfloat16* __restrict__ Bhi, const __nv_bfloat16* __restrict__ Blo,
              float* __restrict__ C, const float* __restrict__ b0, const float* __restrict__ b1,
              __nv_bfloat16* __restrict__ Ohi, __nv_bfloat16* __restrict__ Olo,
              int Nn, int Kk, int col0) {
    extern __shared__ char smem[];
    const int t = threadIdx.x;
    const int bm = blockIdx.y, bn = blockIdx.x;
    const int wid = t >> 5, lane = t & 31;
    const int lr = lane >> 2, lc2 = (lane & 3) << 1;
    const int m0 = (wid >> 1) * 32, n0 = (wid & 1) * 32;

    float acc[2][4][4];
#pragma unroll
    for (int i = 0; i < 2; i++)
#pragma unroll
        for (int j = 0; j < 4; j++)
#pragma unroll
            for (int r = 0; r < 4; r++) acc[i][j][r] = 0.f;

    const uint32_t sb0 = smem_u32(smem);

    // 1536 cp16 units per stage: [0,1024) A hi/lo 128 rows, [1024,1536) B hi/lo 64 rows
    auto load_stage = [&](int stage, int kb) {
#pragma unroll
        for (int i = 0; i < 6; i++) {
            int u = t + i * 256;
            const __nv_bfloat16* src;
            uint32_t dst;
            if (u < 1024) {
                int mat = u >> 9;            // 0 = Ahi, 1 = Alo
                int rem = u & 511;
                int r = rem >> 2, c = rem & 3;
                src = (mat ? Alo : Ahi) + (size_t)(bm * 128 + r) * Kk + kb + c * 8;
                dst = sb0 + stage * STAGEB + mat * MATB_A + r * RS + c * 16;
            } else {
                int u2 = u - 1024;
                int mat = u2 >> 8;           // 0 = Bhi, 1 = Blo
                int rem = u2 & 255;
                int r = rem >> 2, c = rem & 3;
                src = (mat ? Blo : Bhi) + (size_t)(bn * 64 + r) * Kk + kb + c * 8;
                dst = sb0 + stage * STAGEB + 2 * MATB_A + mat * MATB_B + r * RS + c * 16;
            }
            cp16(dst, src);
        }
        CP_COMMIT();
    };

    const int nch = Kk >> 5;
    load_stage(0, 0);

    for (int c = 0; c < nch; c++) {
        if (c + 1 < nch) load_stage((c + 1) & 1, (c + 1) << 5);
        else CP_COMMIT();
        CP_WAIT1();
        __syncthreads();

        const char* sb = smem + (c & 1) * STAGEB;
        const char* pAh = sb;
        const char* pAl = sb + MATB_A;
        const char* pBh = sb + 2 * MATB_A;
        const char* pBl = sb + 2 * MATB_A + MATB_B;
        const int aoff = (m0 + lr) * RS + lc2 * 2;
        const int boff = (n0 + lr) * RS + lc2 * 2;

#pragma unroll
        for (int ks = 0; ks < 2; ks++) {
            const int ko = ks * 32;
            uint32_t bh[4][2], bl[4][2];
#pragma unroll
            for (int nt = 0; nt < 4; nt++) {
                int o = boff + nt * 8 * RS + ko;
                bh[nt][0] = *(const uint32_t*)(pBh + o);
                bh[nt][1] = *(const uint32_t*)(pBh + o + 16);
                bl[nt][0] = *(const uint32_t*)(pBl + o);
                bl[nt][1] = *(const uint32_t*)(pBl + o + 16);
            }
            uint32_t af[2][4];
#pragma unroll
            for (int mt = 0; mt < 2; mt++) {
                int o = aoff + mt * 16 * RS + ko;
                af[mt][0] = *(const uint32_t*)(pAh + o);
                af[mt][1] = *(const uint32_t*)(pAh + o + 8 * RS);
                af[mt][2] = *(const uint32_t*)(pAh + o + 16);
                af[mt][3] = *(const uint32_t*)(pAh + o + 8 * RS + 16);
            }
#pragma unroll
            for (int mt = 0; mt < 2; mt++)
#pragma unroll
                for (int nt = 0; nt < 4; nt++) mma_bf16(acc[mt][nt], af[mt], bh[nt]);
#pragma unroll
            for (int mt = 0; mt < 2; mt++)
#pragma unroll
                for (int nt = 0; nt < 4; nt++) mma_bf16(acc[mt][nt], af[mt], bl[nt]);
#pragma unroll
            for (int mt = 0; mt < 2; mt++) {
                int o = aoff + mt * 16 * RS + ko;
                af[mt][0] = *(const uint32_t*)(pAl + o);
                af[mt][1] = *(const uint32_t*)(pAl + o + 8 * RS);
                af[mt][2] = *(const uint32_t*)(pAl + o + 16);
                af[mt][3] = *(const uint32_t*)(pAl + o + 8 * RS + 16);
            }
#pragma unroll
            for (int mt = 0; mt < 2; mt++)
#pragma unroll
                for (int nt = 0; nt < 4; nt++) mma_bf16(acc[mt][nt], af[mt], bh[nt]);
        }
        __syncthreads();
    }

#pragma unroll
    for (int mt = 0; mt < 2; mt++) {
        int rbase = bm * 128 + m0 + mt * 16 + lr;
#pragma unroll
        for (int nt = 0; nt < 4; nt++) {
            int col = col0 + bn * 64 + n0 + nt * 8 + lc2;
#pragma unroll
            for (int half = 0; half < 2; half++) {
                int row = rbase + half * 8;
                float v0 = acc[mt][nt][half * 2 + 0];
                float v1 = acc[mt][nt][half * 2 + 1];
                if (EPI == 1) {
                    v0 += (col < 384) ? b0[col] : ((col < 768) ? 0.f : b1[col - 768]);
                    int c1 = col + 1;
                    v1 += (c1 < 384) ? b0[c1] : ((c1 < 768) ? 0.f : b1[c1 - 768]);
                    float2 o = {v0, v1};
                    *(float2*)(C + (size_t)row * Nn + col) = o;
                } else if (EPI == 3) {
                    v0 += b0[col];
                    v1 += b0[col + 1];
                    float2 o = {v0, v1};
                    *(float2*)(C + (size_t)row * Nn + col) = o;
                } else {
                    v0 += b0[col];
                    v1 += b0[col + 1];
                    float u0 = v0, u1 = v1;
                    v0 = 0.5f * u0 * (1.0f + fast_tanh(0.7978845608028654f *
                                                       (u0 + 0.044715f * u0 * u0 * u0)));
                    v1 = 0.5f * u1 * (1.0f + fast_tanh(0.7978845608028654f *
                                                       (u1 + 0.044715f * u1 * u1 * u1)));
                    uint32_t lo;
                    uint32_t hi = packsplit_hi(v0, v1, lo);
                    *(uint32_t*)(Ohi + (size_t)row * Nn + col) = hi;
                    *(uint32_t*)(Olo + (size_t)row * Nn + col) = lo;
                }
            }
        }
    }
}

// ---------------- attention on tensor cores (R10 proven) ---------------------
__global__ __launch_bounds__(64)
void attn_kernel(const float* __restrict__ qkv, __nv_bfloat16* __restrict__ ohi,
                 __nv_bfloat16* __restrict__ olo, const float* __restrict__ tab,
                 const float* __restrict__ logit_scale) {
    const int blk = blockIdx.x;
    const int h = blk % 12;
    const int win = blk / 12;
    const int widx = win & 63;
    const int wh8 = (widx >> 3) * 8;
    const int ww8 = (widx & 7) * 8;
    const int t = threadIdx.x;
    const int w = t >> 5, lane = t & 31;
    const int lr = lane >> 2, lq = lane & 3;

    __shared__ __nv_bfloat16 qh[64][40], qlo[64][40];
    __shared__ __nv_bfloat16 kh[64][40], klo[64][40];
    __shared__ __nv_bfloat16 vh[32][72], vlo[32][72];
    __shared__ float tabh[225];

    for (int e = t; e < 225; e += 64) tabh[e] = tab[e * 12 + h];

    {
        const float* qp = qkv + (size_t)(win * 64 + t) * 1152 + h * 32;
        float q[32], k[32], v[32];
#pragma unroll
        for (int i = 0; i < 8; i++) *(float4*)(q + 4 * i) = *(const float4*)(qp + 4 * i);
#pragma unroll
        for (int i = 0; i < 8; i++) *(float4*)(k + 4 * i) = *(const float4*)(qp + 384 + 4 * i);
#pragma unroll
        for (int i = 0; i < 8; i++) *(float4*)(v + 4 * i) = *(const float4*)(qp + 768 + 4 * i);
        float nq = 0.f, nk = 0.f;
#pragma unroll
        for (int d = 0; d < 32; d++) { nq = fmaf(q[d], q[d], nq); nk = fmaf(k[d], k[d], nk); }
        float scale = expf(fminf(logit_scale[h], 4.605170185988091f));
        float rq = rsqrtf(nq) * scale;
        float rk = rsqrtf(nk);
#pragma unroll
        for (int d = 0; d < 32; d += 2) {
            uint32_t lo;
            uint32_t hi = packsplit_hi(q[d] * rq, q[d + 1] * rq, lo);
            *(uint32_t*)&qh[t][d] = hi;
            *(uint32_t*)&qlo[t][d] = lo;
            hi = packsplit_hi(k[d] * rk, k[d + 1] * rk, lo);
            *(uint32_t*)&kh[t][d] = hi;
            *(uint32_t*)&klo[t][d] = lo;
        }
#pragma unroll
        for (int d = 0; d < 32; d++) {
            __nv_bfloat16 hh, ll;
            split2(v[d], hh, ll);
            vh[d][t] = hh;
            vlo[d][t] = ll;
        }
    }
    __syncthreads();

    float s[2][8][4];
#pragma unroll
    for (int mt = 0; mt < 2; mt++)
#pragma unroll
        for (int nt = 0; nt < 8; nt++)
#pragma unroll
            for (int e = 0; e < 4; e++) s[mt][nt][e] = 0.f;

#pragma unroll
    for (int pass = 0; pass < 3; pass++) {
        const char* pQ = (pass == 2) ? (const char*)qlo : (const char*)qh;
        const char* pK = (pass == 1) ? (const char*)klo : (const char*)kh;
#pragma unroll
        for (int ks = 0; ks < 2; ks++) {
            const int ko = lq * 4 + ks * 32;
            uint32_t a[2][4];
#pragma unroll
            for (int mt = 0; mt < 2; mt++) {
                int o = (32 * w + 16 * mt + lr) * 80 + ko;
                a[mt][0] = *(const uint32_t*)(pQ + o);
                a[mt][1] = *(const uint32_t*)(pQ + o + 8 * 80);
                a[mt][2] = *(const uint32_t*)(pQ + o + 16);
                a[mt][3] = *(const uint32_t*)(pQ + o + 8 * 80 + 16);
            }
#pragma unroll
            for (int nt = 0; nt < 8; nt++) {
                int o = (nt * 8 + lr) * 80 + ko;
                uint32_t b[2];
                b[0] = *(const uint32_t*)(pK + o);
                b[1] = *(const uint32_t*)(pK + o + 16);
#pragma unroll
                for (int mt = 0; mt < 2; mt++) mma_bf16(s[mt][nt], a[mt], b);
            }
        }
    }

#pragma unroll
    for (int mt = 0; mt < 2; mt++) {
#pragma unroll
        for (int half = 0; half < 2; half++) {
            const int r = 32 * w + 16 * mt + 8 * half + lr;
            const int ti = r >> 3, tj = r & 7;
            const int labt = shift_label(wh8 + ti, ww8 + tj);
            float mx = -1e30f;
#pragma unroll
            for (int nt = 0; nt < 8; nt++) {
#pragma unroll
                for (int e2 = 0; e2 < 2; e2++) {
                    int u = nt * 8 + lq * 2 + e2;
                    int ui = u >> 3, uj = u & 7;
                    float val = s[mt][nt][half * 2 + e2] +
                                tabh[(tj - uj + 7) * 15 + (ti - ui + 7)];
                    if (shift_label(wh8 + ui, ww8 + uj) != labt) val -= 100.0f;
                    s[mt][nt][half * 2 + e2] = val;
                    mx = fmaxf(mx, val);
                }
            }
            mx = fmaxf(mx, __shfl_xor_sync(0xffffffffu, mx, 1));
            mx = fmaxf(mx, __shfl_xor_sync(0xffffffffu, mx, 2));
            float ss = 0.f;
#pragma unroll
            for (int nt = 0; nt < 8; nt++) {
#pragma unroll
                for (int e2 = 0; e2 < 2; e2++) {
                    float e = __expf(s[mt][nt][half * 2 + e2] - mx);
                    s[mt][nt][half * 2 + e2] = e;
                    ss += e;
                }
            }
            ss += __shfl_xor_sync(0xffffffffu, ss, 1);
            ss += __shfl_xor_sync(0xffffffffu, ss, 2);
            float inv = 1.0f / ss;
#pragma unroll
            for (int nt = 0; nt < 8; nt++) {
#pragma unroll
                for (int e2 = 0; e2 < 2; e2++)
                    s[mt][nt][half * 2 + e2] *= inv;
            }
        }
    }

    uint32_t ph[2][4][4], pl[2][4][4];
#pragma unroll
    for (int mt = 0; mt < 2; mt++)
#pragma unroll
        for (int kb = 0; kb < 4; kb++)
#pragma unroll
            for (int j = 0; j < 4; j++) {
                int nt = 2 * kb + (j >> 1);
                int base = (j & 1) * 2;
                ph[mt][kb][j] = packsplit_hi(s[mt][nt][base], s[mt][nt][base + 1],
                                             pl[mt][kb][j]);
            }

    float o[2][4][4];
#pragma unroll
    for (int mt = 0; mt < 2; mt++)
#pragma unroll
        for (int nt = 0; nt < 4; nt++)
#pragma unroll
            for (int e = 0; e < 4; e++) o[mt][nt][e] = 0.f;

#pragma unroll
    for (int pass = 0; pass < 3; pass++) {
        const uint32_t (*pa)[4][4] = (pass == 2) ? pl : ph;
        const char* pV = (pass == 1) ? (const char*)vlo : (const char*)vh;
#pragma unroll
        for (int kb = 0; kb < 4; kb++) {
#pragma unroll
            for (int nt = 0; nt < 4; nt++) {
                int off = (nt * 8 + lr) * 144 + lq * 4 + kb * 32;
                uint32_t b[2];
                b[0] = *(const uint32_t*)(pV + off);
                b[1] = *(const uint32_t*)(pV + off + 16);
#pragma unroll
                for (int mt = 0; mt < 2; mt++) mma_bf16(o[mt][nt], pa[mt][kb], b);
            }
        }
    }

#pragma unroll
    for (int mt = 0; mt < 2; mt++)
#pragma unroll
        for (int nt = 0; nt < 4; nt++)
#pragma unroll
            for (int half = 0; half < 2; half++) {
                int r = 32 * w + 16 * mt + 8 * half + lr;
                int d = nt * 8 + lq * 2;
                uint32_t lo;
                uint32_t hi = packsplit_hi(o[mt][nt][half * 2], o[mt][nt][half * 2 + 1], lo);
                size_t off = (size_t)(win * 64 + r) * 384 + h * 32 + d;
                *(uint32_t*)(ohi + off) = hi;
                *(uint32_t*)(olo + off) = lo;
            }
}

// ---------------- LayerNorm + residual: warp per token -----------------------
__global__ __launch_bounds__(256)
void ln_res_kernel(const float* __restrict__ y, const float* __restrict__ xin,
                   const float* __restrict__ g, const float* __restrict__ bta,
                   float* __restrict__ out, __nv_bfloat16* __restrict__ ohi,
                   __nv_bfloat16* __restrict__ olo, int mode) {
    const int warp = threadIdx.x >> 5, lane = threadIdx.x & 31;
    const int tok = blockIdx.x * 8 + warp;
    const float* yrow;
    if (mode) {
        int b = tok >> 12, pos = tok & 4095;
        int hc = pos >> 6, wc = pos & 63;
        int hs = (hc + 60) & 63, ws = (wc + 60) & 63;
        int r = (b << 12) + (((hs >> 3) * 8 + (ws >> 3)) << 6) + ((hs & 7) << 3) + (ws & 7);
        yrow = y + (size_t)r * 384;
    } else {
        yrow = y + (size_t)tok * 384;
    }
    float4 v[3];
#pragma unroll
    for (int sgm = 0; sgm < 3; sgm++)
        v[sgm] = *(const float4*)(yrow + (lane + 32 * sgm) * 4);

    float sum = 0.f;
#pragma unroll
    for (int sgm = 0; sgm < 3; sgm++) sum += v[sgm].x + v[sgm].y + v[sgm].z + v[sgm].w;
#pragma unroll
    for (int o2 = 16; o2 > 0; o2 >>= 1) sum += __shfl_xor_sync(0xffffffffu, sum, o2);
    float mu = sum * (1.0f / 384.0f);

    float sq = 0.f;
#pragma unroll
    for (int sgm = 0; sgm < 3; sgm++) {
        v[sgm].x -= mu; v[sgm].y -= mu; v[sgm].z -= mu; v[sgm].w -= mu;
        sq += v[sgm].x * v[sgm].x + v[sgm].y * v[sgm].y +
              v[sgm].z * v[sgm].z + v[sgm].w * v[sgm].w;
    }
#pragma unroll
    for (int o2 = 16; o2 > 0; o2 >>= 1) sq += __shfl_xor_sync(0xffffffffu, sq, o2);
    float inv = rsqrtf(sq * (1.0f / 384.0f) + 1e-6f);

    size_t o_ = (size_t)tok * 384;
#pragma unroll
    for (int sgm = 0; sgm < 3; sgm++) {
        int c = (lane + 32 * sgm) * 4;
        float4 xv = *(const float4*)(xin + o_ + c);
        float4 gv = *(const float4*)(g + c);
        float4 bv = *(const float4*)(bta + c);
        float4 ov;
        ov.x = xv.x + v[sgm].x * inv * gv.x + bv.x;
        ov.y = xv.y + v[sgm].y * inv * gv.y + bv.y;
        ov.z = xv.z + v[sgm].z * inv * gv.z + bv.z;
        ov.w = xv.w + v[sgm].w * inv * gv.w + bv.w;
        *(float4*)(out + o_ + c) = ov;
        if (ohi) {
            uint2 hp, lp;
            hp.x = packsplit_hi(ov.x, ov.y, lp.x);
            hp.y = packsplit_hi(ov.z, ov.w, lp.y);
            *(uint2*)(ohi + o_ + c) = hp;
            *(uint2*)(olo + o_ + c) = lp;
        }
    }
}

// ---------------- launch ----------------------------------------------------
extern "C" void kernel_launch(void* const* d_in, const int* in_sizes, int n_in,
                              void* d_out, int out_size) {
    const float* x        = (const float*)d_in[0];
    const float* qkv_w    = (const float*)d_in[1];
    const float* q_bias   = (const float*)d_in[2];
    const float* v_bias   = (const float*)d_in[3];
    const float* logit_sc = (const float*)d_in[4];
    const float* cpb_w1   = (const float*)d_in[5];
    const float* cpb_b1   = (const float*)d_in[6];
    const float* cpb_w2   = (const float*)d_in[7];
    const float* proj_w   = (const float*)d_in[8];
    const float* proj_b   = (const float*)d_in[9];
    const float* n1s      = (const float*)d_in[10];
    const float* n1b      = (const float*)d_in[11];
    const float* fc1_w    = (const float*)d_in[12];
    const float* fc1_b    = (const float*)d_in[13];
    const float* fc2_w    = (const float*)d_in[14];
    const float* fc2_b    = (const float*)d_in[15];
    const float* n2s      = (const float*)d_in[16];
    const float* n2b      = (const float*)d_in[17];
    float* out = (float*)d_out;

    float *qkv, *y, *x1, *tab;
    __nv_bfloat16 *ahi, *alo, *bhi, *blo, *whi, *wlo;
    cudaGetSymbolAddress((void**)&qkv, g_qkv);
    cudaGetSymbolAddress((void**)&y, g_y);
    cudaGetSymbolAddress((void**)&x1, g_x1);
    cudaGetSymbolAddress((void**)&tab, g_tab);
    cudaGetSymbolAddress((void**)&ahi, g_ahi);
    cudaGetSymbolAddress((void**)&alo, g_alo);
    cudaGetSymbolAddress((void**)&bhi, g_bhi);
    cudaGetSymbolAddress((void**)&blo, g_blo);
    cudaGetSymbolAddress((void**)&whi, g_whi);
    cudaGetSymbolAddress((void**)&wlo, g_wlo);

    cudaFuncSetAttribute(gemm_mma<1>, cudaFuncAttributeMaxDynamicSharedMemorySize, GEMM_SMEM);
    cudaFuncSetAttribute(gemm_mma<2>, cudaFuncAttributeMaxDynamicSharedMemorySize, GEMM_SMEM);
    cudaFuncSetAttribute(gemm_mma<3>, cudaFuncAttributeMaxDynamicSharedMemorySize, GEMM_SMEM);

    wprep_kernel<<<(442368 + 255) / 256, 256>>>(qkv_w, whi + WOFF_QKV, wlo + WOFF_QKV, 384, 1152);
    xprep_kernel<<<M_TOK * 96 / 256, 256>>>(x, ahi, alo);

    gemm_mma<1><<<dim3(10, 1024), 256, GEMM_SMEM>>>(ahi, alo, whi + WOFF_QKV, wlo + WOFF_QKV,
                                                    qkv, q_bias, v_bias, nullptr, nullptr,
                                                    1152, 384, 0);
    gemm_mma<1><<<dim3(8, 1024), 256, GEMM_SMEM>>>(ahi, alo,
                                                   whi + WOFF_QKV + (size_t)640 * 384,
                                                   wlo + WOFF_QKV + (size_t)640 * 384,
                                                   qkv, q_bias, v_bias, nullptr, nullptr,
                                                   1152, 384, 640);

    wprep_kernel<<<(147456 + 255) / 256, 256>>>(proj_w, whi + WOFF_PROJ, wlo + WOFF_PROJ, 384, 384);
    wprep_kernel<<<(589824 + 255) / 256, 256>>>(fc1_w, whi + WOFF_FC1, wlo + WOFF_FC1, 384, 1536);
    wprep_kernel<<<(589824 + 255) / 256, 256>>>(fc2_w, whi + WOFF_FC2, wlo + WOFF_FC2, 1536, 384);
    cpb_kernel<<<1, 256>>>(cpb_w1, cpb_b1, cpb_w2, tab);

    attn_kernel<<<2048 * 12, 64>>>(qkv, ahi, alo, tab, logit_sc);

    gemm_mma<3><<<dim3(6, 1024), 256, GEMM_SMEM>>>(ahi, alo, whi + WOFF_PROJ, wlo + WOFF_PROJ,
                                                   y, proj_b, nullptr, nullptr, nullptr,
                                                   384, 384, 0);

    ln_res_kernel<<<M_TOK / 8, 256>>>(y, x, n1s, n1b, x1, bhi, blo, 1);

    gemm_mma<2><<<dim3(24, 1024), 256, GEMM_SMEM>>>(bhi, blo, whi + WOFF_FC1, wlo + WOFF_FC1,
                                                    nullptr, fc1_b, nullptr, ahi, alo,
                                                    1536, 384, 0);

    gemm_mma<3><<<dim3(6, 1024), 256, GEMM_SMEM>>>(ahi, alo, whi + WOFF_FC2, wlo + WOFF_FC2,
                                                   y, fc2_b, nullptr, nullptr, nullptr,
                                                   384, 1536, 0);

    ln_res_kernel<<<M_TOK / 8, 256>>>(y, x1, n2s, n2b, out, nullptr, nullptr, 0);
}

// round 13
// speedup vs baseline: 1.1334x; 1.1334x over previous
#include <cuda_runtime.h>
#include <cuda_bf16.h>
#include <math.h>
#include <stdint.h>

// ---------------- problem constants -----------------------------------------
#define M_TOK 131072
#define C_DIM 384
#define HID_DIM 1536

// ---------------- scratch ----------------------------------------------------
__device__ float g_qkv[(size_t)M_TOK * 1152];
__device__ float g_y[(size_t)M_TOK * 384];
__device__ float g_x1[(size_t)M_TOK * 384];
__device__ __nv_bfloat16 g_ahi[(size_t)M_TOK * 1536];
__device__ __nv_bfloat16 g_alo[(size_t)M_TOK * 1536];
__device__ __nv_bfloat16 g_bhi[(size_t)M_TOK * 384];
__device__ __nv_bfloat16 g_blo[(size_t)M_TOK * 384];
__device__ __nv_bfloat16 g_whi[1769472];
__device__ __nv_bfloat16 g_wlo[1769472];
__device__ float g_tab[225 * 12];

#define WOFF_QKV 0
#define WOFF_PROJ 442368
#define WOFF_FC1 589824
#define WOFF_FC2 1179648

// ---------------- helpers -----------------------------------------------------
__device__ __forceinline__ uint32_t smem_u32(const void* p) {
    return (uint32_t)__cvta_generic_to_shared(p);
}

__device__ __forceinline__ void cp16(uint32_t dst, const void* src) {
    asm volatile("cp.async.cg.shared.global [%0], [%1], 16;" :: "r"(dst), "l"(src) : "memory");
}
#define CP_COMMIT() asm volatile("cp.async.commit_group;" ::: "memory")
#define CP_WAIT1() asm volatile("cp.async.wait_group 1;" ::: "memory")

__device__ __forceinline__ void mma_bf16(float* d, const uint32_t* a, const uint32_t* b) {
    asm volatile(
        "mma.sync.aligned.m16n8k16.row.col.f32.bf16.bf16.f32 "
        "{%0,%1,%2,%3}, {%4,%5,%6,%7}, {%8,%9}, {%0,%1,%2,%3};"
        : "+f"(d[0]), "+f"(d[1]), "+f"(d[2]), "+f"(d[3])
        : "r"(a[0]), "r"(a[1]), "r"(a[2]), "r"(a[3]), "r"(b[0]), "r"(b[1]));
}

__device__ __forceinline__ void split2(float v, __nv_bfloat16& h, __nv_bfloat16& l) {
    h = __float2bfloat16(v);
    l = __float2bfloat16(v - __bfloat162float(h));
}

__device__ __forceinline__ uint32_t packsplit_hi(float v0, float v1, uint32_t& lo) {
    __nv_bfloat16 h0, l0, h1, l1;
    split2(v0, h0, l0);
    split2(v1, h1, l1);
    __nv_bfloat162 hh = {h0, h1}, ll = {l0, l1};
    lo = *(uint32_t*)&ll;
    return *(uint32_t*)&hh;
}

__device__ __forceinline__ float fast_tanh(float z) {
    return 1.0f - 2.0f / (__expf(2.0f * z) + 1.0f);
}

// ---------------- index maps ------------------------------------------------
__device__ __forceinline__ int qkv_src_row(int r) {
    int b = r >> 12;
    int t = r & 4095;
    int win = t >> 6, p = t & 63;
    int wh = win >> 3, ww = win & 7;
    int i = p >> 3, j = p & 7;
    int h = (wh * 8 + i + 4) & 63;
    int w = (ww * 8 + j + 4) & 63;
    return (b << 12) + (h << 6) + w;
}

__device__ __forceinline__ int shift_label(int hs, int ws) {
    return ((hs < 56) ? 0 : ((hs < 60) ? 1 : 2)) * 3 +
           ((ws < 56) ? 0 : ((ws < 60) ? 1 : 2));
}

// ---------------- CPB table kernel ------------------------------------------
__device__ __forceinline__ float cpb_coord(int v) {
    float x = (float)v * (8.0f / 7.0f);
    float s = (x > 0.f) ? 1.f : ((x < 0.f) ? -1.f : 0.f);
    return s * log2f(fabsf(x) + 1.0f) * (1.0f / 3.0f);
}

__global__ void cpb_kernel(const float* __restrict__ w1, const float* __restrict__ b1,
                           const float* __restrict__ w2, float* __restrict__ tab) {
    int e = blockIdx.x * blockDim.x + threadIdx.x;
    if (e >= 225) return;
    int a = e / 15, b = e % 15;
    float in0 = cpb_coord(b - 7);
    float in1 = cpb_coord(a - 7);
    float out[12];
#pragma unroll
    for (int hh = 0; hh < 12; hh++) out[hh] = 0.f;
    for (int c = 0; c < 512; c++) {
        float hc = fmaf(in0, w1[c], fmaf(in1, w1[512 + c], b1[c]));
        hc = fmaxf(hc, 0.f);
#pragma unroll
        for (int hh = 0; hh < 12; hh++) out[hh] = fmaf(hc, w2[c * 12 + hh], out[hh]);
    }
#pragma unroll
    for (int hh = 0; hh < 12; hh++)
        tab[e * 12 + hh] = 16.0f / (1.0f + expf(-out[hh]));
}

// ---------------- weight prep ------------------------------------------------
__global__ void wprep_kernel(const float* __restrict__ W, __nv_bfloat16* __restrict__ hi,
                             __nv_bfloat16* __restrict__ lo, int K, int N) {
    int u = blockIdx.x * 256 + threadIdx.x;
    if (u >= K * N) return;
    int n = u / K, k = u % K;
    float v = W[(size_t)k * N + n];
    __nv_bfloat16 h, l;
    split2(v, h, l);
    hi[u] = h;
    lo[u] = l;
}

// ---------------- x gather + split -------------------------------------------
__global__ void xprep_kernel(const float* __restrict__ x, __nv_bfloat16* __restrict__ hi,
                             __nv_bfloat16* __restrict__ lo) {
    int u = blockIdx.x * 256 + threadIdx.x;
    int row = u / 96;
    int c4 = u % 96;
    int src = qkv_src_row(row);
    float4 v = *(const float4*)(x + (size_t)src * 384 + c4 * 4);
    uint2 hp, lp;
    hp.x = packsplit_hi(v.x, v.y, lp.x);
    hp.y = packsplit_hi(v.z, v.w, lp.y);
    *(uint2*)(hi + (size_t)row * 384 + c4 * 4) = hp;
    *(uint2*)(lo + (size_t)row * 384 + c4 * 4) = lp;
}

// ---------------- mma.sync split-bf16 GEMM (R11 proven: 128x128, 2 CTA/SM) ---
#define RS 80
#define MATB (128 * RS)
#define STAGEB (4 * MATB)
#define GEMM_SMEM (2 * STAGEB)

template <int EPI>
__global__ __launch_bounds__(256, 2)
void gemm_mma(const __nv_bfloat16* __restrict__ Ahi, const __nv_bfloat16* __restrict__ Alo,
              const __nv_bfloat16* __restrict__ Bhi, const __nv_bfloat16* __restrict__ Blo,
              float* __restrict__ C, const float* __restrict__ b0, const float* __restrict__ b1,
              __nv_bfloat16* __restrict__ Ohi, __nv_bfloat16* __restrict__ Olo,
              int Nn, int Kk, int col0) {
    extern __shared__ char smem[];
    const int t = threadIdx.x;
    const int bm = blockIdx.y, bn = blockIdx.x;
    const int wid = t >> 5, lane = t & 31;
    const int lr = lane >> 2, lc2 = (lane & 3) << 1;
    const int m0 = (wid >> 2) * 64, n0 = (wid & 3) * 32;

    const __nv_bfloat16* srcs[4] = {Ahi, Alo, Bhi, Blo};

    float acc[4][4][4];
#pragma unroll
    for (int i = 0; i < 4; i++)
#pragma unroll
        for (int j = 0; j < 4; j++)
#pragma unroll
            for (int r = 0; r < 4; r++) acc[i][j][r] = 0.f;

    const uint32_t sb0 = smem_u32(smem);

    auto load_stage = [&](int stage, int kb) {
#pragma unroll
        for (int i = 0; i < 8; i++) {
            int u = t + i * 256;
            int mat = u >> 9;
            int rem = u & 511;
            int r = rem >> 2, c = rem & 3;
            int row_g = ((mat < 2) ? bm : bn) * 128 + r;
            const __nv_bfloat16* src = srcs[mat] + (size_t)row_g * Kk + kb + c * 8;
            uint32_t dst = sb0 + stage * STAGEB + mat * MATB + r * RS + c * 16;
            cp16(dst, src);
        }
        CP_COMMIT();
    };

    const int nch = Kk >> 5;
    load_stage(0, 0);

    for (int c = 0; c < nch; c++) {
        if (c + 1 < nch) load_stage((c + 1) & 1, (c + 1) << 5);
        else CP_COMMIT();
        CP_WAIT1();
        __syncthreads();

        const char* sb = smem + (c & 1) * STAGEB;
        const char* pAh = sb;
        const char* pAl = sb + MATB;
        const char* pBh = sb + 2 * MATB;
        const char* pBl = sb + 3 * MATB;
        const int aoff = (m0 + lr) * RS + lc2 * 2;
        const int boff = (n0 + lr) * RS + lc2 * 2;

#pragma unroll
        for (int ks = 0; ks < 2; ks++) {
            const int ko = ks * 32;
            uint32_t bh[4][2], bl[4][2];
#pragma unroll
            for (int nt = 0; nt < 4; nt++) {
                int o = boff + nt * 8 * RS + ko;
                bh[nt][0] = *(const uint32_t*)(pBh + o);
                bh[nt][1] = *(const uint32_t*)(pBh + o + 16);
                bl[nt][0] = *(const uint32_t*)(pBl + o);
                bl[nt][1] = *(const uint32_t*)(pBl + o + 16);
            }
            uint32_t af[4][4];
#pragma unroll
            for (int mt = 0; mt < 4; mt++) {
                int o = aoff + mt * 16 * RS + ko;
                af[mt][0] = *(const uint32_t*)(pAh + o);
                af[mt][1] = *(const uint32_t*)(pAh + o + 8 * RS);
                af[mt][2] = *(const uint32_t*)(pAh + o + 16);
                af[mt][3] = *(const uint32_t*)(pAh + o + 8 * RS + 16);
            }
#pragma unroll
            for (int mt = 0; mt < 4; mt++)
#pragma unroll
                for (int nt = 0; nt < 4; nt++) mma_bf16(acc[mt][nt], af[mt], bh[nt]);
#pragma unroll
            for (int mt = 0; mt < 4; mt++)
#pragma unroll
                for (int nt = 0; nt < 4; nt++) mma_bf16(acc[mt][nt], af[mt], bl[nt]);
#pragma unroll
            for (int mt = 0; mt < 4; mt++) {
                int o = aoff + mt * 16 * RS + ko;
                af[mt][0] = *(const uint32_t*)(pAl + o);
                af[mt][1] = *(const uint32_t*)(pAl + o + 8 * RS);
                af[mt][2] = *(const uint32_t*)(pAl + o + 16);
                af[mt][3] = *(const uint32_t*)(pAl + o + 8 * RS + 16);
            }
#pragma unroll
            for (int mt = 0; mt < 4; mt++)
#pragma unroll
                for (int nt = 0; nt < 4; nt++) mma_bf16(acc[mt][nt], af[mt], bh[nt]);
        }
        __syncthreads();
    }

#pragma unroll
    for (int mt = 0; mt < 4; mt++) {
        int rbase = bm * 128 + m0 + mt * 16 + lr;
#pragma unroll
        for (int nt = 0; nt < 4; nt++) {
            int col = col0 + bn * 128 + n0 + nt * 8 + lc2;
#pragma unroll
            for (int half = 0; half < 2; half++) {
                int row = rbase + half * 8;
                float v0 = acc[mt][nt][half * 2 + 0];
                float v1 = acc[mt][nt][half * 2 + 1];
                if (EPI == 1) {
                    v0 += (col < 384) ? b0[col] : ((col < 768) ? 0.f : b1[col - 768]);
                    int c1 = col + 1;
                    v1 += (c1 < 384) ? b0[c1] : ((c1 < 768) ? 0.f : b1[c1 - 768]);
                    float2 o = {v0, v1};
                    *(float2*)(C + (size_t)row * Nn + col) = o;
                } else if (EPI == 3) {
                    v0 += b0[col];
                    v1 += b0[col + 1];
                    float2 o = {v0, v1};
                    *(float2*)(C + (size_t)row * Nn + col) = o;
                } else {
                    v0 += b0[col];
                    v1 += b0[col + 1];
                    float u0 = v0, u1 = v1;
                    v0 = 0.5f * u0 * (1.0f + fast_tanh(0.7978845608028654f *
                                                       (u0 + 0.044715f * u0 * u0 * u0)));
                    v1 = 0.5f * u1 * (1.0f + fast_tanh(0.7978845608028654f *
                                                       (u1 + 0.044715f * u1 * u1 * u1)));
                    uint32_t lo;
                    uint32_t hi = packsplit_hi(v0, v1, lo);
                    *(uint32_t*)(Ohi + (size_t)row * Nn + col) = hi;
                    *(uint32_t*)(Olo + (size_t)row * Nn + col) = lo;
                }
            }
        }
    }
}

// ---------------- attention on tensor cores (R10 proven) ---------------------
__global__ __launch_bounds__(64)
void attn_kernel(const float* __restrict__ qkv, __nv_bfloat16* __restrict__ ohi,
                 __nv_bfloat16* __restrict__ olo, const float* __restrict__ tab,
                 const float* __restrict__ logit_scale) {
    const int blk = blockIdx.x;
    const int h = blk % 12;
    const int win = blk / 12;
    const int widx = win & 63;
    const int wh8 = (widx >> 3) * 8;
    const int ww8 = (widx & 7) * 8;
    const int t = threadIdx.x;
    const int w = t >> 5, lane = t & 31;
    const int lr = lane >> 2, lq = lane & 3;

    __shared__ __nv_bfloat16 qh[64][40], qlo[64][40];
    __shared__ __nv_bfloat16 kh[64][40], klo[64][40];
    __shared__ __nv_bfloat16 vh[32][72], vlo[32][72];
    __shared__ float tabh[225];

    for (int e = t; e < 225; e += 64) tabh[e] = tab[e * 12 + h];

    {
        const float* qp = qkv + (size_t)(win * 64 + t) * 1152 + h * 32;
        float q[32], k[32], v[32];
#pragma unroll
        for (int i = 0; i < 8; i++) *(float4*)(q + 4 * i) = *(const float4*)(qp + 4 * i);
#pragma unroll
        for (int i = 0; i < 8; i++) *(float4*)(k + 4 * i) = *(const float4*)(qp + 384 + 4 * i);
#pragma unroll
        for (int i = 0; i < 8; i++) *(float4*)(v + 4 * i) = *(const float4*)(qp + 768 + 4 * i);
        float nq = 0.f, nk = 0.f;
#pragma unroll
        for (int d = 0; d < 32; d++) { nq = fmaf(q[d], q[d], nq); nk = fmaf(k[d], k[d], nk); }
        float scale = expf(fminf(logit_scale[h], 4.605170185988091f));
        float rq = rsqrtf(nq) * scale;
        float rk = rsqrtf(nk);
#pragma unroll
        for (int d = 0; d < 32; d += 2) {
            uint32_t lo;
            uint32_t hi = packsplit_hi(q[d] * rq, q[d + 1] * rq, lo);
            *(uint32_t*)&qh[t][d] = hi;
            *(uint32_t*)&qlo[t][d] = lo;
            hi = packsplit_hi(k[d] * rk, k[d + 1] * rk, lo);
            *(uint32_t*)&kh[t][d] = hi;
            *(uint32_t*)&klo[t][d] = lo;
        }
#pragma unroll
        for (int d = 0; d < 32; d++) {
            __nv_bfloat16 hh, ll;
            split2(v[d], hh, ll);
            vh[d][t] = hh;
            vlo[d][t] = ll;
        }
    }
    __syncthreads();

    float s[2][8][4];
#pragma unroll
    for (int mt = 0; mt < 2; mt++)
#pragma unroll
        for (int nt = 0; nt < 8; nt++)
#pragma unroll
            for (int e = 0; e < 4; e++) s[mt][nt][e] = 0.f;

#pragma unroll
    for (int pass = 0; pass < 3; pass++) {
        const char* pQ = (pass == 2) ? (const char*)qlo : (const char*)qh;
        const char* pK = (pass == 1) ? (const char*)klo : (const char*)kh;
#pragma unroll
        for (int ks = 0; ks < 2; ks++) {
            const int ko = lq * 4 + ks * 32;
            uint32_t a[2][4];
#pragma unroll
            for (int mt = 0; mt < 2; mt++) {
                int o = (32 * w + 16 * mt + lr) * 80 + ko;
                a[mt][0] = *(const uint32_t*)(pQ + o);
                a[mt][1] = *(const uint32_t*)(pQ + o + 8 * 80);
                a[mt][2] = *(const uint32_t*)(pQ + o + 16);
                a[mt][3] = *(const uint32_t*)(pQ + o + 8 * 80 + 16);
            }
#pragma unroll
            for (int nt = 0; nt < 8; nt++) {
                int o = (nt * 8 + lr) * 80 + ko;
                uint32_t b[2];
                b[0] = *(const uint32_t*)(pK + o);
                b[1] = *(const uint32_t*)(pK + o + 16);
#pragma unroll
                for (int mt = 0; mt < 2; mt++) mma_bf16(s[mt][nt], a[mt], b);
            }
        }
    }

#pragma unroll
    for (int mt = 0; mt < 2; mt++) {
#pragma unroll
        for (int half = 0; half < 2; half++) {
            const int r = 32 * w + 16 * mt + 8 * half + lr;
            const int ti = r >> 3, tj = r & 7;
            const int labt = shift_label(wh8 + ti, ww8 + tj);
            float mx = -1e30f;
#pragma unroll
            for (int nt = 0; nt < 8; nt++) {
#pragma unroll
                for (int e2 = 0; e2 < 2; e2++) {
                    int u = nt * 8 + lq * 2 + e2;
                    int ui = u >> 3, uj = u & 7;
                    float val = s[mt][nt][half * 2 + e2] +
                                tabh[(tj - uj + 7) * 15 + (ti - ui + 7)];
                    if (shift_label(wh8 + ui, ww8 + uj) != labt) val -= 100.0f;
                    s[mt][nt][half * 2 + e2] = val;
                    mx = fmaxf(mx, val);
                }
            }
            mx = fmaxf(mx, __shfl_xor_sync(0xffffffffu, mx, 1));
            mx = fmaxf(mx, __shfl_xor_sync(0xffffffffu, mx, 2));
            float ss = 0.f;
#pragma unroll
            for (int nt = 0; nt < 8; nt++) {
#pragma unroll
                for (int e2 = 0; e2 < 2; e2++) {
                    float e = __expf(s[mt][nt][half * 2 + e2] - mx);
                    s[mt][nt][half * 2 + e2] = e;
                    ss += e;
                }
            }
            ss += __shfl_xor_sync(0xffffffffu, ss, 1);
            ss += __shfl_xor_sync(0xffffffffu, ss, 2);
            float inv = 1.0f / ss;
#pragma unroll
            for (int nt = 0; nt < 8; nt++) {
#pragma unroll
                for (int e2 = 0; e2 < 2; e2++)
                    s[mt][nt][half * 2 + e2] *= inv;
            }
        }
    }

    uint32_t ph[2][4][4], pl[2][4][4];
#pragma unroll
    for (int mt = 0; mt < 2; mt++)
#pragma unroll
        for (int kb = 0; kb < 4; kb++)
#pragma unroll
            for (int j = 0; j < 4; j++) {
                int nt = 2 * kb + (j >> 1);
                int base = (j & 1) * 2;
                ph[mt][kb][j] = packsplit_hi(s[mt][nt][base], s[mt][nt][base + 1],
                                             pl[mt][kb][j]);
            }

    float o[2][4][4];
#pragma unroll
    for (int mt = 0; mt < 2; mt++)
#pragma unroll
        for (int nt = 0; nt < 4; nt++)
#pragma unroll
            for (int e = 0; e < 4; e++) o[mt][nt][e] = 0.f;

#pragma unroll
    for (int pass = 0; pass < 3; pass++) {
        const uint32_t (*pa)[4][4] = (pass == 2) ? pl : ph;
        const char* pV = (pass == 1) ? (const char*)vlo : (const char*)vh;
#pragma unroll
        for (int kb = 0; kb < 4; kb++) {
#pragma unroll
            for (int nt = 0; nt < 4; nt++) {
                int off = (nt * 8 + lr) * 144 + lq * 4 + kb * 32;
                uint32_t b[2];
                b[0] = *(const uint32_t*)(pV + off);
                b[1] = *(const uint32_t*)(pV + off + 16);
#pragma unroll
                for (int mt = 0; mt < 2; mt++) mma_bf16(o[mt][nt], pa[mt][kb], b);
            }
        }
    }

#pragma unroll
    for (int mt = 0; mt < 2; mt++)
#pragma unroll
        for (int nt = 0; nt < 4; nt++)
#pragma unroll
            for (int half = 0; half < 2; half++) {
                int r = 32 * w + 16 * mt + 8 * half + lr;
                int d = nt * 8 + lq * 2;
                uint32_t lo;
                uint32_t hi = packsplit_hi(o[mt][nt][half * 2], o[mt][nt][half * 2 + 1], lo);
                size_t off = (size_t)(win * 64 + r) * 384 + h * 32 + d;
                *(uint32_t*)(ohi + off) = hi;
                *(uint32_t*)(olo + off) = lo;
            }
}

// ---------------- LayerNorm + residual: warp per token -----------------------
__global__ __launch_bounds__(256)
void ln_res_kernel(const float* __restrict__ y, const float* __restrict__ xin,
                   const float* __restrict__ g, const float* __restrict__ bta,
                   float* __restrict__ out, __nv_bfloat16* __restrict__ ohi,
                   __nv_bfloat16* __restrict__ olo, int mode) {
    const int warp = threadIdx.x >> 5, lane = threadIdx.x & 31;
    const int tok = blockIdx.x * 8 + warp;
    const float* yrow;
    if (mode) {
        int b = tok >> 12, pos = tok & 4095;
        int hc = pos >> 6, wc = pos & 63;
        int hs = (hc + 60) & 63, ws = (wc + 60) & 63;
        int r = (b << 12) + (((hs >> 3) * 8 + (ws >> 3)) << 6) + ((hs & 7) << 3) + (ws & 7);
        yrow = y + (size_t)r * 384;
    } else {
        yrow = y + (size_t)tok * 384;
    }
    float4 v[3];
#pragma unroll
    for (int sgm = 0; sgm < 3; sgm++)
        v[sgm] = *(const float4*)(yrow + (lane + 32 * sgm) * 4);

    float sum = 0.f;
#pragma unroll
    for (int sgm = 0; sgm < 3; sgm++) sum += v[sgm].x + v[sgm].y + v[sgm].z + v[sgm].w;
#pragma unroll
    for (int o2 = 16; o2 > 0; o2 >>= 1) sum += __shfl_xor_sync(0xffffffffu, sum, o2);
    float mu = sum * (1.0f / 384.0f);

    float sq = 0.f;
#pragma unroll
    for (int sgm = 0; sgm < 3; sgm++) {
        v[sgm].x -= mu; v[sgm].y -= mu; v[sgm].z -= mu; v[sgm].w -= mu;
        sq += v[sgm].x * v[sgm].x + v[sgm].y * v[sgm].y +
              v[sgm].z * v[sgm].z + v[sgm].w * v[sgm].w;
    }
#pragma unroll
    for (int o2 = 16; o2 > 0; o2 >>= 1) sq += __shfl_xor_sync(0xffffffffu, sq, o2);
    float inv = rsqrtf(sq * (1.0f / 384.0f) + 1e-6f);

    size_t o_ = (size_t)tok * 384;
#pragma unroll
    for (int sgm = 0; sgm < 3; sgm++) {
        int c = (lane + 32 * sgm) * 4;
        float4 xv = *(const float4*)(xin + o_ + c);
        float4 gv = *(const float4*)(g + c);
        float4 bv = *(const float4*)(bta + c);
        float4 ov;
        ov.x = xv.x + v[sgm].x * inv * gv.x + bv.x;
        ov.y = xv.y + v[sgm].y * inv * gv.y + bv.y;
        ov.z = xv.z + v[sgm].z * inv * gv.z + bv.z;
        ov.w = xv.w + v[sgm].w * inv * gv.w + bv.w;
        *(float4*)(out + o_ + c) = ov;
        if (ohi) {
            uint2 hp, lp;
            hp.x = packsplit_hi(ov.x, ov.y, lp.x);
            hp.y = packsplit_hi(ov.z, ov.w, lp.y);
            *(uint2*)(ohi + o_ + c) = hp;
            *(uint2*)(olo + o_ + c) = lp;
        }
    }
}

// ---------------- launch ----------------------------------------------------
extern "C" void kernel_launch(void* const* d_in, const int* in_sizes, int n_in,
                              void* d_out, int out_size) {
    const float* x        = (const float*)d_in[0];
    const float* qkv_w    = (const float*)d_in[1];
    const float* q_bias   = (const float*)d_in[2];
    const float* v_bias   = (const float*)d_in[3];
    const float* logit_sc = (const float*)d_in[4];
    const float* cpb_w1   = (const float*)d_in[5];
    const float* cpb_b1   = (const float*)d_in[6];
    const float* cpb_w2   = (const float*)d_in[7];
    const float* proj_w   = (const float*)d_in[8];
    const float* proj_b   = (const float*)d_in[9];
    const float* n1s      = (const float*)d_in[10];
    const float* n1b      = (const float*)d_in[11];
    const float* fc1_w    = (const float*)d_in[12];
    const float* fc1_b    = (const float*)d_in[13];
    const float* fc2_w    = (const float*)d_in[14];
    const float* fc2_b    = (const float*)d_in[15];
    const float* n2s      = (const float*)d_in[16];
    const float* n2b      = (const float*)d_in[17];
    float* out = (float*)d_out;

    float *qkv, *y, *x1, *tab;
    __nv_bfloat16 *ahi, *alo, *bhi, *blo, *whi, *wlo;
    cudaGetSymbolAddress((void**)&qkv, g_qkv);
    cudaGetSymbolAddress((void**)&y, g_y);
    cudaGetSymbolAddress((void**)&x1, g_x1);
    cudaGetSymbolAddress((void**)&tab, g_tab);
    cudaGetSymbolAddress((void**)&ahi, g_ahi);
    cudaGetSymbolAddress((void**)&alo, g_alo);
    cudaGetSymbolAddress((void**)&bhi, g_bhi);
    cudaGetSymbolAddress((void**)&blo, g_blo);
    cudaGetSymbolAddress((void**)&whi, g_whi);
    cudaGetSymbolAddress((void**)&wlo, g_wlo);

    cudaFuncSetAttribute(gemm_mma<1>, cudaFuncAttributeMaxDynamicSharedMemorySize, GEMM_SMEM);
    cudaFuncSetAttribute(gemm_mma<2>, cudaFuncAttributeMaxDynamicSharedMemorySize, GEMM_SMEM);
    cudaFuncSetAttribute(gemm_mma<3>, cudaFuncAttributeMaxDynamicSharedMemorySize, GEMM_SMEM);

    wprep_kernel<<<(442368 + 255) / 256, 256>>>(qkv_w, whi + WOFF_QKV, wlo + WOFF_QKV, 384, 1152);
    xprep_kernel<<<M_TOK * 96 / 256, 256>>>(x, ahi, alo);

    // QKV gemm: single launch (R11 config)
    gemm_mma<1><<<dim3(9, 1024), 256, GEMM_SMEM>>>(ahi, alo, whi + WOFF_QKV, wlo + WOFF_QKV,
                                                   qkv, q_bias, v_bias, nullptr, nullptr,
                                                   1152, 384, 0);

    wprep_kernel<<<(147456 + 255) / 256, 256>>>(proj_w, whi + WOFF_PROJ, wlo + WOFF_PROJ, 384, 384);
    wprep_kernel<<<(589824 + 255) / 256, 256>>>(fc1_w, whi + WOFF_FC1, wlo + WOFF_FC1, 384, 1536);
    wprep_kernel<<<(589824 + 255) / 256, 256>>>(fc2_w, whi + WOFF_FC2, wlo + WOFF_FC2, 1536, 384);
    cpb_kernel<<<1, 256>>>(cpb_w1, cpb_b1, cpb_w2, tab);

    attn_kernel<<<2048 * 12, 64>>>(qkv, ahi, alo, tab, logit_sc);

    gemm_mma<3><<<dim3(3, 1024), 256, GEMM_SMEM>>>(ahi, alo, whi + WOFF_PROJ, wlo + WOFF_PROJ,
                                                   y, proj_b, nullptr, nullptr, nullptr,
                                                   384, 384, 0);

    ln_res_kernel<<<M_TOK / 8, 256>>>(y, x, n1s, n1b, x1, bhi, blo, 1);

    gemm_mma<2><<<dim3(12, 1024), 256, GEMM_SMEM>>>(bhi, blo, whi + WOFF_FC1, wlo + WOFF_FC1,
                                                    nullptr, fc1_b, nullptr, ahi, alo,
                                                    1536, 384, 0);

    gemm_mma<3><<<dim3(3, 1024), 256, GEMM_SMEM>>>(ahi, alo, whi + WOFF_FC2, wlo + WOFF_FC2,
                                                   y, fc2_b, nullptr, nullptr, nullptr,
                                                   384, 1536, 0);

    ln_res_kernel<<<M_TOK / 8, 256>>>(y, x1, n2s, n2b, out, nullptr, nullptr, 0);
}

// round 14
// speedup vs baseline: 1.3452x; 1.1869x over previous
#include <cuda_runtime.h>
#include <cuda_bf16.h>
#include <cuda_fp16.h>
#include <math.h>
#include <stdint.h>

// ---------------- problem constants -----------------------------------------
#define M_TOK 131072
#define C_DIM 384
#define HID_DIM 1536

// ---------------- scratch ----------------------------------------------------
__device__ float g_qkv[(size_t)M_TOK * 1152];
__device__ float g_y[(size_t)M_TOK * 384];
__device__ float g_x1[(size_t)M_TOK * 384];
__device__ __half g_ahi[(size_t)M_TOK * 1536];
__device__ __half g_alo[(size_t)M_TOK * 1536];
__device__ __half g_bhi[(size_t)M_TOK * 384];
__device__ __half g_blo[(size_t)M_TOK * 384];
__device__ __half g_whi[1769472];
__device__ __half g_wlo[1769472];
__device__ float g_tab[225 * 12];

#define WOFF_QKV 0
#define WOFF_PROJ 442368
#define WOFF_FC1 589824
#define WOFF_FC2 1179648

// ---------------- helpers -----------------------------------------------------
__device__ __forceinline__ uint32_t smem_u32(const void* p) {
    return (uint32_t)__cvta_generic_to_shared(p);
}

__device__ __forceinline__ void cp16(uint32_t dst, const void* src) {
    asm volatile("cp.async.cg.shared.global [%0], [%1], 16;" :: "r"(dst), "l"(src) : "memory");
}
#define CP_COMMIT() asm volatile("cp.async.commit_group;" ::: "memory")
#define CP_WAIT1() asm volatile("cp.async.wait_group 1;" ::: "memory")

// fp16 mma (GEMM path)
__device__ __forceinline__ void mma_f16(float* d, const uint32_t* a, const uint32_t* b) {
    asm volatile(
        "mma.sync.aligned.m16n8k16.row.col.f32.f16.f16.f32 "
        "{%0,%1,%2,%3}, {%4,%5,%6,%7}, {%8,%9}, {%0,%1,%2,%3};"
        : "+f"(d[0]), "+f"(d[1]), "+f"(d[2]), "+f"(d[3])
        : "r"(a[0]), "r"(a[1]), "r"(a[2]), "r"(a[3]), "r"(b[0]), "r"(b[1]));
}

// bf16 mma (attention path, proven)
__device__ __forceinline__ void mma_bf16(float* d, const uint32_t* a, const uint32_t* b) {
    asm volatile(
        "mma.sync.aligned.m16n8k16.row.col.f32.bf16.bf16.f32 "
        "{%0,%1,%2,%3}, {%4,%5,%6,%7}, {%8,%9}, {%0,%1,%2,%3};"
        : "+f"(d[0]), "+f"(d[1]), "+f"(d[2]), "+f"(d[3])
        : "r"(a[0]), "r"(a[1]), "r"(a[2]), "r"(a[3]), "r"(b[0]), "r"(b[1]));
}

// bf16 split (attention internals)
__device__ __forceinline__ void split2b(float v, __nv_bfloat16& h, __nv_bfloat16& l) {
    h = __float2bfloat16(v);
    l = __float2bfloat16(v - __bfloat162float(h));
}
__device__ __forceinline__ uint32_t packsplit_b(float v0, float v1, uint32_t& lo) {
    __nv_bfloat16 h0, l0, h1, l1;
    split2b(v0, h0, l0);
    split2b(v1, h1, l1);
    __nv_bfloat162 hh = {h0, h1}, ll = {l0, l1};
    lo = *(uint32_t*)&ll;
    return *(uint32_t*)&hh;
}

// fp16 split (GEMM operands)
__device__ __forceinline__ void split2h(float v, __half& h, __half& l) {
    h = __float2half(v);
    l = __float2half(v - __half2float(h));
}
__device__ __forceinline__ uint32_t packsplit_h(float v0, float v1, uint32_t& lo) {
    __half h0, l0, h1, l1;
    split2h(v0, h0, l0);
    split2h(v1, h1, l1);
    __half2 hh = {h0, h1}, ll = {l0, l1};
    lo = *(uint32_t*)&ll;
    return *(uint32_t*)&hh;
}

__device__ __forceinline__ float fast_tanh(float z) {
    return 1.0f - 2.0f / (__expf(2.0f * z) + 1.0f);
}

// ---------------- index maps ------------------------------------------------
__device__ __forceinline__ int qkv_src_row(int r) {
    int b = r >> 12;
    int t = r & 4095;
    int win = t >> 6, p = t & 63;
    int wh = win >> 3, ww = win & 7;
    int i = p >> 3, j = p & 7;
    int h = (wh * 8 + i + 4) & 63;
    int w = (ww * 8 + j + 4) & 63;
    return (b << 12) + (h << 6) + w;
}

__device__ __forceinline__ int shift_label(int hs, int ws) {
    return ((hs < 56) ? 0 : ((hs < 60) ? 1 : 2)) * 3 +
           ((ws < 56) ? 0 : ((ws < 60) ? 1 : 2));
}

// ---------------- CPB table kernel ------------------------------------------
__device__ __forceinline__ float cpb_coord(int v) {
    float x = (float)v * (8.0f / 7.0f);
    float s = (x > 0.f) ? 1.f : ((x < 0.f) ? -1.f : 0.f);
    return s * log2f(fabsf(x) + 1.0f) * (1.0f / 3.0f);
}

__global__ void cpb_kernel(const float* __restrict__ w1, const float* __restrict__ b1,
                           const float* __restrict__ w2, float* __restrict__ tab) {
    int e = blockIdx.x * blockDim.x + threadIdx.x;
    if (e >= 225) return;
    int a = e / 15, b = e % 15;
    float in0 = cpb_coord(b - 7);
    float in1 = cpb_coord(a - 7);
    float out[12];
#pragma unroll
    for (int hh = 0; hh < 12; hh++) out[hh] = 0.f;
    for (int c = 0; c < 512; c++) {
        float hc = fmaf(in0, w1[c], fmaf(in1, w1[512 + c], b1[c]));
        hc = fmaxf(hc, 0.f);
#pragma unroll
        for (int hh = 0; hh < 12; hh++) out[hh] = fmaf(hc, w2[c * 12 + hh], out[hh]);
    }
#pragma unroll
    for (int hh = 0; hh < 12; hh++)
        tab[e * 12 + hh] = 16.0f / (1.0f + expf(-out[hh]));
}

// ---------------- weight prep: W[K,N] -> Wt[N,K] fp16 hi/lo ------------------
__global__ void wprep_kernel(const float* __restrict__ W, __half* __restrict__ hi,
                             __half* __restrict__ lo, int K, int N) {
    int u = blockIdx.x * 256 + threadIdx.x;
    if (u >= K * N) return;
    int n = u / K, k = u % K;
    float v = W[(size_t)k * N + n];
    __half h, l;
    split2h(v, h, l);
    hi[u] = h;
    lo[u] = l;
}

// ---------------- x gather + split -------------------------------------------
__global__ void xprep_kernel(const float* __restrict__ x, __half* __restrict__ hi,
                             __half* __restrict__ lo) {
    int u = blockIdx.x * 256 + threadIdx.x;
    int row = u / 96;
    int c4 = u % 96;
    int src = qkv_src_row(row);
    float4 v = *(const float4*)(x + (size_t)src * 384 + c4 * 4);
    uint2 hp, lp;
    hp.x = packsplit_h(v.x, v.y, lp.x);
    hp.y = packsplit_h(v.z, v.w, lp.y);
    *(uint2*)(hi + (size_t)row * 384 + c4 * 4) = hp;
    *(uint2*)(lo + (size_t)row * 384 + c4 * 4) = lp;
}

// ---------------- mma.sync split-fp16 GEMM -----------------------------------
// TERMS=3: D = AhBh + AhBl + AlBh (QKV; dropped lo*lo ~2^-22)
// TERMS=2: D = (Ah+Al)Bh (proj/fc1/fc2; dropped A*Bl ~2^-12.6 rms)
// 128x128 CTA tile, 64x32 warp tiles (R11 proven optimum), 2 CTAs/SM.
#define RS 80
#define MATB (128 * RS)

template <int EPI, int TERMS>
__global__ __launch_bounds__(256, 2)
void gemm_mma(const __half* __restrict__ Ahi, const __half* __restrict__ Alo,
              const __half* __restrict__ Bhi, const __half* __restrict__ Blo,
              float* __restrict__ C, const float* __restrict__ b0, const float* __restrict__ b1,
              __half* __restrict__ Ohi, __half* __restrict__ Olo,
              int Nn, int Kk, int col0) {
    constexpr int NMAT = TERMS + 1;        // 3-term: Ah Al Bh Bl; 2-term: Ah Al Bh
    constexpr int STB = NMAT * MATB;
    extern __shared__ char smem[];
    const int t = threadIdx.x;
    const int bm = blockIdx.y, bn = blockIdx.x;
    const int wid = t >> 5, lane = t & 31;
    const int lr = lane >> 2, lc2 = (lane & 3) << 1;
    const int m0 = (wid >> 2) * 64, n0 = (wid & 3) * 32;

    const __half* srcs[4] = {Ahi, Alo, Bhi, Blo};

    float acc[4][4][4];
#pragma unroll
    for (int i = 0; i < 4; i++)
#pragma unroll
        for (int j = 0; j < 4; j++)
#pragma unroll
            for (int r = 0; r < 4; r++) acc[i][j][r] = 0.f;

    const uint32_t sb0 = smem_u32(smem);

    auto load_stage = [&](int stage, int kb) {
#pragma unroll
        for (int i = 0; i < 2 * NMAT; i++) {
            int u = t + i * 256;           // 0 .. NMAT*512-1
            int mat = u >> 9;
            int rem = u & 511;
            int r = rem >> 2, c = rem & 3;
            int row_g = ((mat < 2) ? bm : bn) * 128 + r;
            const __half* src = srcs[mat] + (size_t)row_g * Kk + kb + c * 8;
            uint32_t dst = sb0 + stage * STB + mat * MATB + r * RS + c * 16;
            cp16(dst, src);
        }
        CP_COMMIT();
    };

    const int nch = Kk >> 5;
    load_stage(0, 0);

    for (int c = 0; c < nch; c++) {
        if (c + 1 < nch) load_stage((c + 1) & 1, (c + 1) << 5);
        else CP_COMMIT();
        CP_WAIT1();
        __syncthreads();

        const char* sb = smem + (c & 1) * STB;
        const char* pAh = sb;
        const char* pAl = sb + MATB;
        const char* pBh = sb + 2 * MATB;
        const char* pBl = sb + 3 * MATB;   // unused when TERMS==2
        const int aoff = (m0 + lr) * RS + lc2 * 2;
        const int boff = (n0 + lr) * RS + lc2 * 2;

#pragma unroll
        for (int ks = 0; ks < 2; ks++) {
            const int ko = ks * 32;
            uint32_t bh[4][2];
#pragma unroll
            for (int nt = 0; nt < 4; nt++) {
                int o = boff + nt * 8 * RS + ko;
                bh[nt][0] = *(const uint32_t*)(pBh + o);
                bh[nt][1] = *(const uint32_t*)(pBh + o + 16);
            }
            uint32_t af[4][4];
#pragma unroll
            for (int mt = 0; mt < 4; mt++) {
                int o = aoff + mt * 16 * RS + ko;
                af[mt][0] = *(const uint32_t*)(pAh + o);
                af[mt][1] = *(const uint32_t*)(pAh + o + 8 * RS);
                af[mt][2] = *(const uint32_t*)(pAh + o + 16);
                af[mt][3] = *(const uint32_t*)(pAh + o + 8 * RS + 16);
            }
#pragma unroll
            for (int mt = 0; mt < 4; mt++)
#pragma unroll
                for (int nt = 0; nt < 4; nt++) mma_f16(acc[mt][nt], af[mt], bh[nt]);
            if (TERMS == 3) {
                uint32_t bl[4][2];
#pragma unroll
                for (int nt = 0; nt < 4; nt++) {
                    int o = boff + nt * 8 * RS + ko;
                    bl[nt][0] = *(const uint32_t*)(pBl + o);
                    bl[nt][1] = *(const uint32_t*)(pBl + o + 16);
                }
#pragma unroll
                for (int mt = 0; mt < 4; mt++)
#pragma unroll
                    for (int nt = 0; nt < 4; nt++) mma_f16(acc[mt][nt], af[mt], bl[nt]);
            }
#pragma unroll
            for (int mt = 0; mt < 4; mt++) {
                int o = aoff + mt * 16 * RS + ko;
                af[mt][0] = *(const uint32_t*)(pAl + o);
                af[mt][1] = *(const uint32_t*)(pAl + o + 8 * RS);
                af[mt][2] = *(const uint32_t*)(pAl + o + 16);
                af[mt][3] = *(const uint32_t*)(pAl + o + 8 * RS + 16);
            }
#pragma unroll
            for (int mt = 0; mt < 4; mt++)
#pragma unroll
                for (int nt = 0; nt < 4; nt++) mma_f16(acc[mt][nt], af[mt], bh[nt]);
        }
        __syncthreads();
    }

#pragma unroll
    for (int mt = 0; mt < 4; mt++) {
        int rbase = bm * 128 + m0 + mt * 16 + lr;
#pragma unroll
        for (int nt = 0; nt < 4; nt++) {
            int col = col0 + bn * 128 + n0 + nt * 8 + lc2;
#pragma unroll
            for (int half = 0; half < 2; half++) {
                int row = rbase + half * 8;
                float v0 = acc[mt][nt][half * 2 + 0];
                float v1 = acc[mt][nt][half * 2 + 1];
                if (EPI == 1) {
                    v0 += (col < 384) ? b0[col] : ((col < 768) ? 0.f : b1[col - 768]);
                    int c1 = col + 1;
                    v1 += (c1 < 384) ? b0[c1] : ((c1 < 768) ? 0.f : b1[c1 - 768]);
                    float2 o = {v0, v1};
                    *(float2*)(C + (size_t)row * Nn + col) = o;
                } else if (EPI == 3) {
                    v0 += b0[col];
                    v1 += b0[col + 1];
                    float2 o = {v0, v1};
                    *(float2*)(C + (size_t)row * Nn + col) = o;
                } else {
                    v0 += b0[col];
                    v1 += b0[col + 1];
                    float u0 = v0, u1 = v1;
                    v0 = 0.5f * u0 * (1.0f + fast_tanh(0.7978845608028654f *
                                                       (u0 + 0.044715f * u0 * u0 * u0)));
                    v1 = 0.5f * u1 * (1.0f + fast_tanh(0.7978845608028654f *
                                                       (u1 + 0.044715f * u1 * u1 * u1)));
                    uint32_t lo;
                    uint32_t hi = packsplit_h(v0, v1, lo);
                    *(uint32_t*)(Ohi + (size_t)row * Nn + col) = hi;
                    *(uint32_t*)(Olo + (size_t)row * Nn + col) = lo;
                }
            }
        }
    }
}

// ---------------- attention on tensor cores (R10 proven; fp16 output) --------
__global__ __launch_bounds__(64)
void attn_kernel(const float* __restrict__ qkv, __half* __restrict__ ohi,
                 __half* __restrict__ olo, const float* __restrict__ tab,
                 const float* __restrict__ logit_scale) {
    const int blk = blockIdx.x;
    const int h = blk % 12;
    const int win = blk / 12;
    const int widx = win & 63;
    const int wh8 = (widx >> 3) * 8;
    const int ww8 = (widx & 7) * 8;
    const int t = threadIdx.x;
    const int w = t >> 5, lane = t & 31;
    const int lr = lane >> 2, lq = lane & 3;

    __shared__ __nv_bfloat16 qh[64][40], qlo[64][40];
    __shared__ __nv_bfloat16 kh[64][40], klo[64][40];
    __shared__ __nv_bfloat16 vh[32][72], vlo[32][72];
    __shared__ float tabh[225];

    for (int e = t; e < 225; e += 64) tabh[e] = tab[e * 12 + h];

    {
        const float* qp = qkv + (size_t)(win * 64 + t) * 1152 + h * 32;
        float q[32], k[32], v[32];
#pragma unroll
        for (int i = 0; i < 8; i++) *(float4*)(q + 4 * i) = *(const float4*)(qp + 4 * i);
#pragma unroll
        for (int i = 0; i < 8; i++) *(float4*)(k + 4 * i) = *(const float4*)(qp + 384 + 4 * i);
#pragma unroll
        for (int i = 0; i < 8; i++) *(float4*)(v + 4 * i) = *(const float4*)(qp + 768 + 4 * i);
        float nq = 0.f, nk = 0.f;
#pragma unroll
        for (int d = 0; d < 32; d++) { nq = fmaf(q[d], q[d], nq); nk = fmaf(k[d], k[d], nk); }
        float scale = expf(fminf(logit_scale[h], 4.605170185988091f));
        float rq = rsqrtf(nq) * scale;
        float rk = rsqrtf(nk);
#pragma unroll
        for (int d = 0; d < 32; d += 2) {
            uint32_t lo;
            uint32_t hi = packsplit_b(q[d] * rq, q[d + 1] * rq, lo);
            *(uint32_t*)&qh[t][d] = hi;
            *(uint32_t*)&qlo[t][d] = lo;
            hi = packsplit_b(k[d] * rk, k[d + 1] * rk, lo);
            *(uint32_t*)&kh[t][d] = hi;
            *(uint32_t*)&klo[t][d] = lo;
        }
#pragma unroll
        for (int d = 0; d < 32; d++) {
            __nv_bfloat16 hh, ll;
            split2b(v[d], hh, ll);
            vh[d][t] = hh;
            vlo[d][t] = ll;
        }
    }
    __syncthreads();

    float s[2][8][4];
#pragma unroll
    for (int mt = 0; mt < 2; mt++)
#pragma unroll
        for (int nt = 0; nt < 8; nt++)
#pragma unroll
            for (int e = 0; e < 4; e++) s[mt][nt][e] = 0.f;

#pragma unroll
    for (int pass = 0; pass < 3; pass++) {
        const char* pQ = (pass == 2) ? (const char*)qlo : (const char*)qh;
        const char* pK = (pass == 1) ? (const char*)klo : (const char*)kh;
#pragma unroll
        for (int ks = 0; ks < 2; ks++) {
            const int ko = lq * 4 + ks * 32;
            uint32_t a[2][4];
#pragma unroll
            for (int mt = 0; mt < 2; mt++) {
                int o = (32 * w + 16 * mt + lr) * 80 + ko;
                a[mt][0] = *(const uint32_t*)(pQ + o);
                a[mt][1] = *(const uint32_t*)(pQ + o + 8 * 80);
                a[mt][2] = *(const uint32_t*)(pQ + o + 16);
                a[mt][3] = *(const uint32_t*)(pQ + o + 8 * 80 + 16);
            }
#pragma unroll
            for (int nt = 0; nt < 8; nt++) {
                int o = (nt * 8 + lr) * 80 + ko;
                uint32_t b[2];
                b[0] = *(const uint32_t*)(pK + o);
                b[1] = *(const uint32_t*)(pK + o + 16);
#pragma unroll
                for (int mt = 0; mt < 2; mt++) mma_bf16(s[mt][nt], a[mt], b);
            }
        }
    }

#pragma unroll
    for (int mt = 0; mt < 2; mt++) {
#pragma unroll
        for (int half = 0; half < 2; half++) {
            const int r = 32 * w + 16 * mt + 8 * half + lr;
            const int ti = r >> 3, tj = r & 7;
            const int labt = shift_label(wh8 + ti, ww8 + tj);
            float mx = -1e30f;
#pragma unroll
            for (int nt = 0; nt < 8; nt++) {
#pragma unroll
                for (int e2 = 0; e2 < 2; e2++) {
                    int u = nt * 8 + lq * 2 + e2;
                    int ui = u >> 3, uj = u & 7;
                    float val = s[mt][nt][half * 2 + e2] +
                                tabh[(tj - uj + 7) * 15 + (ti - ui + 7)];
                    if (shift_label(wh8 + ui, ww8 + uj) != labt) val -= 100.0f;
                    s[mt][nt][half * 2 + e2] = val;
                    mx = fmaxf(mx, val);
                }
            }
            mx = fmaxf(mx, __shfl_xor_sync(0xffffffffu, mx, 1));
            mx = fmaxf(mx, __shfl_xor_sync(0xffffffffu, mx, 2));
            float ss = 0.f;
#pragma unroll
            for (int nt = 0; nt < 8; nt++) {
#pragma unroll
                for (int e2 = 0; e2 < 2; e2++) {
                    float e = __expf(s[mt][nt][half * 2 + e2] - mx);
                    s[mt][nt][half * 2 + e2] = e;
                    ss += e;
                }
            }
            ss += __shfl_xor_sync(0xffffffffu, ss, 1);
            ss += __shfl_xor_sync(0xffffffffu, ss, 2);
            float inv = 1.0f / ss;
#pragma unroll
            for (int nt = 0; nt < 8; nt++) {
#pragma unroll
                for (int e2 = 0; e2 < 2; e2++)
                    s[mt][nt][half * 2 + e2] *= inv;
            }
        }
    }

    uint32_t ph[2][4][4], pl[2][4][4];
#pragma unroll
    for (int mt = 0; mt < 2; mt++)
#pragma unroll
        for (int kb = 0; kb < 4; kb++)
#pragma unroll
            for (int j = 0; j < 4; j++) {
                int nt = 2 * kb + (j >> 1);
                int base = (j & 1) * 2;
                ph[mt][kb][j] = packsplit_b(s[mt][nt][base], s[mt][nt][base + 1],
                                            pl[mt][kb][j]);
            }

    float o[2][4][4];
#pragma unroll
    for (int mt = 0; mt < 2; mt++)
#pragma unroll
        for (int nt = 0; nt < 4; nt++)
#pragma unroll
            for (int e = 0; e < 4; e++) o[mt][nt][e] = 0.f;

#pragma unroll
    for (int pass = 0; pass < 3; pass++) {
        const uint32_t (*pa)[4][4] = (pass == 2) ? pl : ph;
        const char* pV = (pass == 1) ? (const char*)vlo : (const char*)vh;
#pragma unroll
        for (int kb = 0; kb < 4; kb++) {
#pragma unroll
            for (int nt = 0; nt < 4; nt++) {
                int off = (nt * 8 + lr) * 144 + lq * 4 + kb * 32;
                uint32_t b[2];
                b[0] = *(const uint32_t*)(pV + off);
                b[1] = *(const uint32_t*)(pV + off + 16);
#pragma unroll
                for (int mt = 0; mt < 2; mt++) mma_bf16(o[mt][nt], pa[mt][kb], b);
            }
        }
    }

#pragma unroll
    for (int mt = 0; mt < 2; mt++)
#pragma unroll
        for (int nt = 0; nt < 4; nt++)
#pragma unroll
            for (int half = 0; half < 2; half++) {
                int r = 32 * w + 16 * mt + 8 * half + lr;
                int d = nt * 8 + lq * 2;
                uint32_t lo;
                uint32_t hi = packsplit_h(o[mt][nt][half * 2], o[mt][nt][half * 2 + 1], lo);
                size_t off = (size_t)(win * 64 + r) * 384 + h * 32 + d;
                *(uint32_t*)(ohi + off) = hi;
                *(uint32_t*)(olo + off) = lo;
            }
}

// ---------------- LayerNorm + residual: warp per token -----------------------
__global__ __launch_bounds__(256)
void ln_res_kernel(const float* __restrict__ y, const float* __restrict__ xin,
                   const float* __restrict__ g, const float* __restrict__ bta,
                   float* __restrict__ out, __half* __restrict__ ohi,
                   __half* __restrict__ olo, int mode) {
    const int warp = threadIdx.x >> 5, lane = threadIdx.x & 31;
    const int tok = blockIdx.x * 8 + warp;
    const float* yrow;
    if (mode) {
        int b = tok >> 12, pos = tok & 4095;
        int hc = pos >> 6, wc = pos & 63;
        int hs = (hc + 60) & 63, ws = (wc + 60) & 63;
        int r = (b << 12) + (((hs >> 3) * 8 + (ws >> 3)) << 6) + ((hs & 7) << 3) + (ws & 7);
        yrow = y + (size_t)r * 384;
    } else {
        yrow = y + (size_t)tok * 384;
    }
    float4 v[3];
#pragma unroll
    for (int sgm = 0; sgm < 3; sgm++)
        v[sgm] = *(const float4*)(yrow + (lane + 32 * sgm) * 4);

    float sum = 0.f;
#pragma unroll
    for (int sgm = 0; sgm < 3; sgm++) sum += v[sgm].x + v[sgm].y + v[sgm].z + v[sgm].w;
#pragma unroll
    for (int o2 = 16; o2 > 0; o2 >>= 1) sum += __shfl_xor_sync(0xffffffffu, sum, o2);
    float mu = sum * (1.0f / 384.0f);

    float sq = 0.f;
#pragma unroll
    for (int sgm = 0; sgm < 3; sgm++) {
        v[sgm].x -= mu; v[sgm].y -= mu; v[sgm].z -= mu; v[sgm].w -= mu;
        sq += v[sgm].x * v[sgm].x + v[sgm].y * v[sgm].y +
              v[sgm].z * v[sgm].z + v[sgm].w * v[sgm].w;
    }
#pragma unroll
    for (int o2 = 16; o2 > 0; o2 >>= 1) sq += __shfl_xor_sync(0xffffffffu, sq, o2);
    float inv = rsqrtf(sq * (1.0f / 384.0f) + 1e-6f);

    size_t o_ = (size_t)tok * 384;
#pragma unroll
    for (int sgm = 0; sgm < 3; sgm++) {
        int c = (lane + 32 * sgm) * 4;
        float4 xv = *(const float4*)(xin + o_ + c);
        float4 gv = *(const float4*)(g + c);
        float4 bv = *(const float4*)(bta + c);
        float4 ov;
        ov.x = xv.x + v[sgm].x * inv * gv.x + bv.x;
        ov.y = xv.y + v[sgm].y * inv * gv.y + bv.y;
        ov.z = xv.z + v[sgm].z * inv * gv.z + bv.z;
        ov.w = xv.w + v[sgm].w * inv * gv.w + bv.w;
        *(float4*)(out + o_ + c) = ov;
        if (ohi) {
            uint2 hp, lp;
            hp.x = packsplit_h(ov.x, ov.y, lp.x);
            hp.y = packsplit_h(ov.z, ov.w, lp.y);
            *(uint2*)(ohi + o_ + c) = hp;
            *(uint2*)(olo + o_ + c) = lp;
        }
    }
}

// ---------------- launch ----------------------------------------------------
#define GEMM_SMEM3 (2 * 4 * MATB)   // 81920
#define GEMM_SMEM2 (2 * 3 * MATB)   // 61440

extern "C" void kernel_launch(void* const* d_in, const int* in_sizes, int n_in,
                              void* d_out, int out_size) {
    const float* x        = (const float*)d_in[0];
    const float* qkv_w    = (const float*)d_in[1];
    const float* q_bias   = (const float*)d_in[2];
    const float* v_bias   = (const float*)d_in[3];
    const float* logit_sc = (const float*)d_in[4];
    const float* cpb_w1   = (const float*)d_in[5];
    const float* cpb_b1   = (const float*)d_in[6];
    const float* cpb_w2   = (const float*)d_in[7];
    const float* proj_w   = (const float*)d_in[8];
    const float* proj_b   = (const float*)d_in[9];
    const float* n1s      = (const float*)d_in[10];
    const float* n1b      = (const float*)d_in[11];
    const float* fc1_w    = (const float*)d_in[12];
    const float* fc1_b    = (const float*)d_in[13];
    const float* fc2_w    = (const float*)d_in[14];
    const float* fc2_b    = (const float*)d_in[15];
    const float* n2s      = (const float*)d_in[16];
    const float* n2b      = (const float*)d_in[17];
    float* out = (float*)d_out;

    float *qkv, *y, *x1, *tab;
    __half *ahi, *alo, *bhi, *blo, *whi, *wlo;
    cudaGetSymbolAddress((void**)&qkv, g_qkv);
    cudaGetSymbolAddress((void**)&y, g_y);
    cudaGetSymbolAddress((void**)&x1, g_x1);
    cudaGetSymbolAddress((void**)&tab, g_tab);
    cudaGetSymbolAddress((void**)&ahi, g_ahi);
    cudaGetSymbolAddress((void**)&alo, g_alo);
    cudaGetSymbolAddress((void**)&bhi, g_bhi);
    cudaGetSymbolAddress((void**)&blo, g_blo);
    cudaGetSymbolAddress((void**)&whi, g_whi);
    cudaGetSymbolAddress((void**)&wlo, g_wlo);

    cudaFuncSetAttribute(gemm_mma<1, 3>, cudaFuncAttributeMaxDynamicSharedMemorySize, GEMM_SMEM3);
    cudaFuncSetAttribute(gemm_mma<2, 2>, cudaFuncAttributeMaxDynamicSharedMemorySize, GEMM_SMEM2);
    cudaFuncSetAttribute(gemm_mma<3, 2>, cudaFuncAttributeMaxDynamicSharedMemorySize, GEMM_SMEM2);

    wprep_kernel<<<(442368 + 255) / 256, 256>>>(qkv_w, whi + WOFF_QKV, wlo + WOFF_QKV, 384, 1152);
    xprep_kernel<<<M_TOK * 96 / 256, 256>>>(x, ahi, alo);

    // QKV: fp16 3-term (Q/K feed the x10 logit-scale amplification)
    gemm_mma<1, 3><<<dim3(9, 1024), 256, GEMM_SMEM3>>>(ahi, alo, whi + WOFF_QKV, wlo + WOFF_QKV,
                                                       qkv, q_bias, v_bias, nullptr, nullptr,
                                                       1152, 384, 0);

    wprep_kernel<<<(147456 + 255) / 256, 256>>>(proj_w, whi + WOFF_PROJ, wlo + WOFF_PROJ, 384, 384);
    wprep_kernel<<<(589824 + 255) / 256, 256>>>(fc1_w, whi + WOFF_FC1, wlo + WOFF_FC1, 384, 1536);
    wprep_kernel<<<(589824 + 255) / 256, 256>>>(fc2_w, whi + WOFF_FC2, wlo + WOFF_FC2, 1536, 384);
    cpb_kernel<<<1, 256>>>(cpb_w1, cpb_b1, cpb_w2, tab);

    attn_kernel<<<2048 * 12, 64>>>(qkv, ahi, alo, tab, logit_sc);

    // proj / fc1 / fc2: fp16 2-term (no exponential amplification downstream)
    gemm_mma<3, 2><<<dim3(3, 1024), 256, GEMM_SMEM2>>>(ahi, alo, whi + WOFF_PROJ, wlo + WOFF_PROJ,
                                                       y, proj_b, nullptr, nullptr, nullptr,
                                                       384, 384, 0);

    ln_res_kernel<<<M_TOK / 8, 256>>>(y, x, n1s, n1b, x1, bhi, blo, 1);

    gemm_mma<2, 2><<<dim3(12, 1024), 256, GEMM_SMEM2>>>(bhi, blo, whi + WOFF_FC1, wlo + WOFF_FC1,
                                                        nullptr, fc1_b, nullptr, ahi, alo,
                                                        1536, 384, 0);

    gemm_mma<3, 2><<<dim3(3, 1024), 256, GEMM_SMEM2>>>(ahi, alo, whi + WOFF_FC2, wlo + WOFF_FC2,
                                                       y, fc2_b, nullptr, nullptr, nullptr,
                                                       384, 1536, 0);

    ln_res_kernel<<<M_TOK / 8, 256>>>(y, x1, n2s, n2b, out, nullptr, nullptr, 0);
}

// round 15
// speedup vs baseline: 1.4157x; 1.0524x over previous
#include <cuda_runtime.h>
#include <cuda_bf16.h>
#include <cuda_fp16.h>
#include <math.h>
#include <stdint.h>

// ---------------- problem constants -----------------------------------------
#define M_TOK 131072
#define C_DIM 384
#define HID_DIM 1536

// ---------------- scratch ----------------------------------------------------
__device__ float g_qkv[(size_t)M_TOK * 1152];
__device__ float g_y[(size_t)M_TOK * 384];
__device__ float g_x1[(size_t)M_TOK * 384];
__device__ __half g_ahi[(size_t)M_TOK * 1536];
__device__ __half g_alo[(size_t)M_TOK * 1536];
__device__ __half g_bhi[(size_t)M_TOK * 384];
__device__ __half g_blo[(size_t)M_TOK * 384];
__device__ __half g_whi[1769472];
__device__ __half g_wlo[1769472];
__device__ float g_tab[225 * 12];

#define WOFF_QKV 0
#define WOFF_PROJ 442368
#define WOFF_FC1 589824
#define WOFF_FC2 1179648

// ---------------- helpers -----------------------------------------------------
__device__ __forceinline__ uint32_t smem_u32(const void* p) {
    return (uint32_t)__cvta_generic_to_shared(p);
}

__device__ __forceinline__ void cp16(uint32_t dst, const void* src) {
    asm volatile("cp.async.cg.shared.global [%0], [%1], 16;" :: "r"(dst), "l"(src) : "memory");
}
#define CP_COMMIT() asm volatile("cp.async.commit_group;" ::: "memory")
#define CP_WAIT1() asm volatile("cp.async.wait_group 1;" ::: "memory")

__device__ __forceinline__ void mma_f16(float* d, const uint32_t* a, const uint32_t* b) {
    asm volatile(
        "mma.sync.aligned.m16n8k16.row.col.f32.f16.f16.f32 "
        "{%0,%1,%2,%3}, {%4,%5,%6,%7}, {%8,%9}, {%0,%1,%2,%3};"
        : "+f"(d[0]), "+f"(d[1]), "+f"(d[2]), "+f"(d[3])
        : "r"(a[0]), "r"(a[1]), "r"(a[2]), "r"(a[3]), "r"(b[0]), "r"(b[1]));
}

__device__ __forceinline__ void mma_bf16(float* d, const uint32_t* a, const uint32_t* b) {
    asm volatile(
        "mma.sync.aligned.m16n8k16.row.col.f32.bf16.bf16.f32 "
        "{%0,%1,%2,%3}, {%4,%5,%6,%7}, {%8,%9}, {%0,%1,%2,%3};"
        : "+f"(d[0]), "+f"(d[1]), "+f"(d[2]), "+f"(d[3])
        : "r"(a[0]), "r"(a[1]), "r"(a[2]), "r"(a[3]), "r"(b[0]), "r"(b[1]));
}

__device__ __forceinline__ void split2b(float v, __nv_bfloat16& h, __nv_bfloat16& l) {
    h = __float2bfloat16(v);
    l = __float2bfloat16(v - __bfloat162float(h));
}
__device__ __forceinline__ uint32_t packsplit_b(float v0, float v1, uint32_t& lo) {
    __nv_bfloat16 h0, l0, h1, l1;
    split2b(v0, h0, l0);
    split2b(v1, h1, l1);
    __nv_bfloat162 hh = {h0, h1}, ll = {l0, l1};
    lo = *(uint32_t*)&ll;
    return *(uint32_t*)&hh;
}

__device__ __forceinline__ void split2h(float v, __half& h, __half& l) {
    h = __float2half(v);
    l = __float2half(v - __half2float(h));
}
__device__ __forceinline__ uint32_t packsplit_h(float v0, float v1, uint32_t& lo) {
    __half h0, l0, h1, l1;
    split2h(v0, h0, l0);
    split2h(v1, h1, l1);
    __half2 hh = {h0, h1}, ll = {l0, l1};
    lo = *(uint32_t*)&ll;
    return *(uint32_t*)&hh;
}

__device__ __forceinline__ float fast_tanh(float z) {
    return 1.0f - 2.0f / (__expf(2.0f * z) + 1.0f);
}

// ---------------- index maps ------------------------------------------------
__device__ __forceinline__ int qkv_src_row(int r) {
    int b = r >> 12;
    int t = r & 4095;
    int win = t >> 6, p = t & 63;
    int wh = win >> 3, ww = win & 7;
    int i = p >> 3, j = p & 7;
    int h = (wh * 8 + i + 4) & 63;
    int w = (ww * 8 + j + 4) & 63;
    return (b << 12) + (h << 6) + w;
}

__device__ __forceinline__ int shift_label(int hs, int ws) {
    return ((hs < 56) ? 0 : ((hs < 60) ? 1 : 2)) * 3 +
           ((ws < 56) ? 0 : ((ws < 60) ? 1 : 2));
}

// ---------------- CPB table kernel ------------------------------------------
__device__ __forceinline__ float cpb_coord(int v) {
    float x = (float)v * (8.0f / 7.0f);
    float s = (x > 0.f) ? 1.f : ((x < 0.f) ? -1.f : 0.f);
    return s * log2f(fabsf(x) + 1.0f) * (1.0f / 3.0f);
}

__global__ void cpb_kernel(const float* __restrict__ w1, const float* __restrict__ b1,
                           const float* __restrict__ w2, float* __restrict__ tab) {
    int e = blockIdx.x * blockDim.x + threadIdx.x;
    if (e >= 225) return;
    int a = e / 15, b = e % 15;
    float in0 = cpb_coord(b - 7);
    float in1 = cpb_coord(a - 7);
    float out[12];
#pragma unroll
    for (int hh = 0; hh < 12; hh++) out[hh] = 0.f;
    for (int c = 0; c < 512; c++) {
        float hc = fmaf(in0, w1[c], fmaf(in1, w1[512 + c], b1[c]));
        hc = fmaxf(hc, 0.f);
#pragma unroll
        for (int hh = 0; hh < 12; hh++) out[hh] = fmaf(hc, w2[c * 12 + hh], out[hh]);
    }
#pragma unroll
    for (int hh = 0; hh < 12; hh++)
        tab[e * 12 + hh] = 16.0f / (1.0f + expf(-out[hh]));
}

// ---------------- weight prep ------------------------------------------------
__global__ void wprep_kernel(const float* __restrict__ W, __half* __restrict__ hi,
                             __half* __restrict__ lo, int K, int N) {
    int u = blockIdx.x * 256 + threadIdx.x;
    if (u >= K * N) return;
    int n = u / K, k = u % K;
    float v = W[(size_t)k * N + n];
    __half h, l;
    split2h(v, h, l);
    hi[u] = h;
    lo[u] = l;
}

// ---------------- x gather + split -------------------------------------------
__global__ void xprep_kernel(const float* __restrict__ x, __half* __restrict__ hi,
                             __half* __restrict__ lo) {
    int u = blockIdx.x * 256 + threadIdx.x;
    int row = u / 96;
    int c4 = u % 96;
    int src = qkv_src_row(row);
    float4 v = *(const float4*)(x + (size_t)src * 384 + c4 * 4);
    uint2 hp, lp;
    hp.x = packsplit_h(v.x, v.y, lp.x);
    hp.y = packsplit_h(v.z, v.w, lp.y);
    *(uint2*)(hi + (size_t)row * 384 + c4 * 4) = hp;
    *(uint2*)(lo + (size_t)row * 384 + c4 * 4) = lp;
}

// ---------------- mma.sync split-fp16 GEMM -----------------------------------
// TERMS=3 (QKV): D = AhBh + AhBl + AlBh; K-chunk 32, RS 80, 4 smem matrices.
// TERMS=2 (proj/fc1/fc2): D = (Ah+Al)Bh; K-chunk 64, RS 144 (R3-proven layout,
//   quad-pattern banks 4*lr+q all distinct), 3 smem matrices -> half the syncs.
// 128x128 CTA tile, 64x32 warp tiles (R11 proven optimum), 2 CTAs/SM.
template <int EPI, int TERMS>
__global__ __launch_bounds__(256, 2)
void gemm_mma(const __half* __restrict__ Ahi, const __half* __restrict__ Alo,
              const __half* __restrict__ Bhi, const __half* __restrict__ Blo,
              float* __restrict__ C, const float* __restrict__ b0, const float* __restrict__ b1,
              __half* __restrict__ Ohi, __half* __restrict__ Olo,
              int Nn, int Kk, int col0) {
    constexpr int NMAT = TERMS + 1;                 // 4 or 3
    constexpr int KC = (TERMS == 3) ? 32 : 64;      // K-chunk
    constexpr int RSv = (TERMS == 3) ? 80 : 144;    // smem row stride bytes
    constexpr int MB = 128 * RSv;                   // bytes per matrix
    constexpr int STB = NMAT * MB;                  // bytes per stage
    constexpr int CPR = KC / 8;                     // 16B chunks per row
    constexpr int UNITS = NMAT * 128 * CPR;         // cp16 units per stage
    extern __shared__ char smem[];
    const int t = threadIdx.x;
    const int bm = blockIdx.y, bn = blockIdx.x;
    const int wid = t >> 5, lane = t & 31;
    const int lr = lane >> 2, lc2 = (lane & 3) << 1;
    const int m0 = (wid >> 2) * 64, n0 = (wid & 3) * 32;

    const __half* srcs[4] = {Ahi, Alo, Bhi, Blo};

    float acc[4][4][4];
#pragma unroll
    for (int i = 0; i < 4; i++)
#pragma unroll
        for (int j = 0; j < 4; j++)
#pragma unroll
            for (int r = 0; r < 4; r++) acc[i][j][r] = 0.f;

    const uint32_t sb0 = smem_u32(smem);

    auto load_stage = [&](int stage, int kb) {
#pragma unroll
        for (int i = 0; i < UNITS / 256; i++) {
            int u = t + i * 256;
            int mat = u / (128 * CPR);
            int rem = u % (128 * CPR);
            int r = rem / CPR, c = rem % CPR;
            int row_g = ((mat < 2) ? bm : bn) * 128 + r;
            const __half* src = srcs[mat] + (size_t)row_g * Kk + kb + c * 8;
            uint32_t dst = sb0 + stage * STB + mat * MB + r * RSv + c * 16;
            cp16(dst, src);
        }
        CP_COMMIT();
    };

    const int nch = Kk / KC;
    load_stage(0, 0);

    for (int c = 0; c < nch; c++) {
        if (c + 1 < nch) load_stage((c + 1) & 1, (c + 1) * KC);
        else CP_COMMIT();
        CP_WAIT1();
        __syncthreads();

        const char* sb = smem + (c & 1) * STB;
        const char* pAh = sb;
        const char* pAl = sb + MB;
        const char* pBh = sb + 2 * MB;
        const char* pBl = sb + 3 * MB;     // unused when TERMS==2
        const int aoff = (m0 + lr) * RSv + lc2 * 2;
        const int boff = (n0 + lr) * RSv + lc2 * 2;

#pragma unroll
        for (int ks = 0; ks < KC / 16; ks++) {
            const int ko = ks * 32;
            uint32_t bh[4][2];
#pragma unroll
            for (int nt = 0; nt < 4; nt++) {
                int o = boff + nt * 8 * RSv + ko;
                bh[nt][0] = *(const uint32_t*)(pBh + o);
                bh[nt][1] = *(const uint32_t*)(pBh + o + 16);
            }
            uint32_t af[4][4];
#pragma unroll
            for (int mt = 0; mt < 4; mt++) {
                int o = aoff + mt * 16 * RSv + ko;
                af[mt][0] = *(const uint32_t*)(pAh + o);
                af[mt][1] = *(const uint32_t*)(pAh + o + 8 * RSv);
                af[mt][2] = *(const uint32_t*)(pAh + o + 16);
                af[mt][3] = *(const uint32_t*)(pAh + o + 8 * RSv + 16);
            }
#pragma unroll
            for (int mt = 0; mt < 4; mt++)
#pragma unroll
                for (int nt = 0; nt < 4; nt++) mma_f16(acc[mt][nt], af[mt], bh[nt]);
            if (TERMS == 3) {
                uint32_t bl[4][2];
#pragma unroll
                for (int nt = 0; nt < 4; nt++) {
                    int o = boff + nt * 8 * RSv + ko;
                    bl[nt][0] = *(const uint32_t*)(pBl + o);
                    bl[nt][1] = *(const uint32_t*)(pBl + o + 16);
                }
#pragma unroll
                for (int mt = 0; mt < 4; mt++)
#pragma unroll
                    for (int nt = 0; nt < 4; nt++) mma_f16(acc[mt][nt], af[mt], bl[nt]);
            }
#pragma unroll
            for (int mt = 0; mt < 4; mt++) {
                int o = aoff + mt * 16 * RSv + ko;
                af[mt][0] = *(const uint32_t*)(pAl + o);
                af[mt][1] = *(const uint32_t*)(pAl + o + 8 * RSv);
                af[mt][2] = *(const uint32_t*)(pAl + o + 16);
                af[mt][3] = *(const uint32_t*)(pAl + o + 8 * RSv + 16);
            }
#pragma unroll
            for (int mt = 0; mt < 4; mt++)
#pragma unroll
                for (int nt = 0; nt < 4; nt++) mma_f16(acc[mt][nt], af[mt], bh[nt]);
        }
        __syncthreads();
    }

#pragma unroll
    for (int mt = 0; mt < 4; mt++) {
        int rbase = bm * 128 + m0 + mt * 16 + lr;
#pragma unroll
        for (int nt = 0; nt < 4; nt++) {
            int col = col0 + bn * 128 + n0 + nt * 8 + lc2;
#pragma unroll
            for (int half = 0; half < 2; half++) {
                int row = rbase + half * 8;
                float v0 = acc[mt][nt][half * 2 + 0];
                float v1 = acc[mt][nt][half * 2 + 1];
                if (EPI == 1) {
                    v0 += (col < 384) ? b0[col] : ((col < 768) ? 0.f : b1[col - 768]);
                    int c1 = col + 1;
                    v1 += (c1 < 384) ? b0[c1] : ((c1 < 768) ? 0.f : b1[c1 - 768]);
                    float2 o = {v0, v1};
                    *(float2*)(C + (size_t)row * Nn + col) = o;
                } else if (EPI == 3) {
                    v0 += b0[col];
                    v1 += b0[col + 1];
                    float2 o = {v0, v1};
                    *(float2*)(C + (size_t)row * Nn + col) = o;
                } else {
                    v0 += b0[col];
                    v1 += b0[col + 1];
                    float u0 = v0, u1 = v1;
                    v0 = 0.5f * u0 * (1.0f + fast_tanh(0.7978845608028654f *
                                                       (u0 + 0.044715f * u0 * u0 * u0)));
                    v1 = 0.5f * u1 * (1.0f + fast_tanh(0.7978845608028654f *
                                                       (u1 + 0.044715f * u1 * u1 * u1)));
                    uint32_t lo;
                    uint32_t hi = packsplit_h(v0, v1, lo);
                    *(uint32_t*)(Ohi + (size_t)row * Nn + col) = hi;
                    *(uint32_t*)(Olo + (size_t)row * Nn + col) = lo;
                }
            }
        }
    }
}

// ---------------- attention on tensor cores (R10 proven; fp16 output) --------
__global__ __launch_bounds__(64)
void attn_kernel(const float* __restrict__ qkv, __half* __restrict__ ohi,
                 __half* __restrict__ olo, const float* __restrict__ tab,
                 const float* __restrict__ logit_scale) {
    const int blk = blockIdx.x;
    const int h = blk % 12;
    const int win = blk / 12;
    const int widx = win & 63;
    const int wh8 = (widx >> 3) * 8;
    const int ww8 = (widx & 7) * 8;
    const int t = threadIdx.x;
    const int w = t >> 5, lane = t & 31;
    const int lr = lane >> 2, lq = lane & 3;

    __shared__ __nv_bfloat16 qh[64][40], qlo[64][40];
    __shared__ __nv_bfloat16 kh[64][40], klo[64][40];
    __shared__ __nv_bfloat16 vh[32][72], vlo[32][72];
    __shared__ float tabh[225];

    for (int e = t; e < 225; e += 64) tabh[e] = tab[e * 12 + h];

    {
        const float* qp = qkv + (size_t)(win * 64 + t) * 1152 + h * 32;
        float q[32], k[32], v[32];
#pragma unroll
        for (int i = 0; i < 8; i++) *(float4*)(q + 4 * i) = *(const float4*)(qp + 4 * i);
#pragma unroll
        for (int i = 0; i < 8; i++) *(float4*)(k + 4 * i) = *(const float4*)(qp + 384 + 4 * i);
#pragma unroll
        for (int i = 0; i < 8; i++) *(float4*)(v + 4 * i) = *(const float4*)(qp + 768 + 4 * i);
        float nq = 0.f, nk = 0.f;
#pragma unroll
        for (int d = 0; d < 32; d++) { nq = fmaf(q[d], q[d], nq); nk = fmaf(k[d], k[d], nk); }
        float scale = expf(fminf(logit_scale[h], 4.605170185988091f));
        float rq = rsqrtf(nq) * scale;
        float rk = rsqrtf(nk);
#pragma unroll
        for (int d = 0; d < 32; d += 2) {
            uint32_t lo;
            uint32_t hi = packsplit_b(q[d] * rq, q[d + 1] * rq, lo);
            *(uint32_t*)&qh[t][d] = hi;
            *(uint32_t*)&qlo[t][d] = lo;
            hi = packsplit_b(k[d] * rk, k[d + 1] * rk, lo);
            *(uint32_t*)&kh[t][d] = hi;
            *(uint32_t*)&klo[t][d] = lo;
        }
#pragma unroll
        for (int d = 0; d < 32; d++) {
            __nv_bfloat16 hh, ll;
            split2b(v[d], hh, ll);
            vh[d][t] = hh;
            vlo[d][t] = ll;
        }
    }
    __syncthreads();

    float s[2][8][4];
#pragma unroll
    for (int mt = 0; mt < 2; mt++)
#pragma unroll
        for (int nt = 0; nt < 8; nt++)
#pragma unroll
            for (int e = 0; e < 4; e++) s[mt][nt][e] = 0.f;

#pragma unroll
    for (int pass = 0; pass < 3; pass++) {
        const char* pQ = (pass == 2) ? (const char*)qlo : (const char*)qh;
        const char* pK = (pass == 1) ? (const char*)klo : (const char*)kh;
#pragma unroll
        for (int ks = 0; ks < 2; ks++) {
            const int ko = lq * 4 + ks * 32;
            uint32_t a[2][4];
#pragma unroll
            for (int mt = 0; mt < 2; mt++) {
                int o = (32 * w + 16 * mt + lr) * 80 + ko;
                a[mt][0] = *(const uint32_t*)(pQ + o);
                a[mt][1] = *(const uint32_t*)(pQ + o + 8 * 80);
                a[mt][2] = *(const uint32_t*)(pQ + o + 16);
                a[mt][3] = *(const uint32_t*)(pQ + o + 8 * 80 + 16);
            }
#pragma unroll
            for (int nt = 0; nt < 8; nt++) {
                int o = (nt * 8 + lr) * 80 + ko;
                uint32_t b[2];
                b[0] = *(const uint32_t*)(pK + o);
                b[1] = *(const uint32_t*)(pK + o + 16);
#pragma unroll
                for (int mt = 0; mt < 2; mt++) mma_bf16(s[mt][nt], a[mt], b);
            }
        }
    }

#pragma unroll
    for (int mt = 0; mt < 2; mt++) {
#pragma unroll
        for (int half = 0; half < 2; half++) {
            const int r = 32 * w + 16 * mt + 8 * half + lr;
            const int ti = r >> 3, tj = r & 7;
            const int labt = shift_label(wh8 + ti, ww8 + tj);
            float mx = -1e30f;
#pragma unroll
            for (int nt = 0; nt < 8; nt++) {
#pragma unroll
                for (int e2 = 0; e2 < 2; e2++) {
                    int u = nt * 8 + lq * 2 + e2;
                    int ui = u >> 3, uj = u & 7;
                    float val = s[mt][nt][half * 2 + e2] +
                                tabh[(tj - uj + 7) * 15 + (ti - ui + 7)];
                    if (shift_label(wh8 + ui, ww8 + uj) != labt) val -= 100.0f;
                    s[mt][nt][half * 2 + e2] = val;
                    mx = fmaxf(mx, val);
                }
            }
            mx = fmaxf(mx, __shfl_xor_sync(0xffffffffu, mx, 1));
            mx = fmaxf(mx, __shfl_xor_sync(0xffffffffu, mx, 2));
            float ss = 0.f;
#pragma unroll
            for (int nt = 0; nt < 8; nt++) {
#pragma unroll
                for (int e2 = 0; e2 < 2; e2++) {
                    float e = __expf(s[mt][nt][half * 2 + e2] - mx);
                    s[mt][nt][half * 2 + e2] = e;
                    ss += e;
                }
            }
            ss += __shfl_xor_sync(0xffffffffu, ss, 1);
            ss += __shfl_xor_sync(0xffffffffu, ss, 2);
            float inv = 1.0f / ss;
#pragma unroll
            for (int nt = 0; nt < 8; nt++) {
#pragma unroll
                for (int e2 = 0; e2 < 2; e2++)
                    s[mt][nt][half * 2 + e2] *= inv;
            }
        }
    }

    uint32_t ph[2][4][4], pl[2][4][4];
#pragma unroll
    for (int mt = 0; mt < 2; mt++)
#pragma unroll
        for (int kb = 0; kb < 4; kb++)
#pragma unroll
            for (int j = 0; j < 4; j++) {
                int nt = 2 * kb + (j >> 1);
                int base = (j & 1) * 2;
                ph[mt][kb][j] = packsplit_b(s[mt][nt][base], s[mt][nt][base + 1],
                                            pl[mt][kb][j]);
            }

    float o[2][4][4];
#pragma unroll
    for (int mt = 0; mt < 2; mt++)
#pragma unroll
        for (int nt = 0; nt < 4; nt++)
#pragma unroll
            for (int e = 0; e < 4; e++) o[mt][nt][e] = 0.f;

#pragma unroll
    for (int pass = 0; pass < 3; pass++) {
        const uint32_t (*pa)[4][4] = (pass == 2) ? pl : ph;
        const char* pV = (pass == 1) ? (const char*)vlo : (const char*)vh;
#pragma unroll
        for (int kb = 0; kb < 4; kb++) {
#pragma unroll
            for (int nt = 0; nt < 4; nt++) {
                int off = (nt * 8 + lr) * 144 + lq * 4 + kb * 32;
                uint32_t b[2];
                b[0] = *(const uint32_t*)(pV + off);
                b[1] = *(const uint32_t*)(pV + off + 16);
#pragma unroll
                for (int mt = 0; mt < 2; mt++) mma_bf16(o[mt][nt], pa[mt][kb], b);
            }
        }
    }

#pragma unroll
    for (int mt = 0; mt < 2; mt++)
#pragma unroll
        for (int nt = 0; nt < 4; nt++)
#pragma unroll
            for (int half = 0; half < 2; half++) {
                int r = 32 * w + 16 * mt + 8 * half + lr;
                int d = nt * 8 + lq * 2;
                uint32_t lo;
                uint32_t hi = packsplit_h(o[mt][nt][half * 2], o[mt][nt][half * 2 + 1], lo);
                size_t off = (size_t)(win * 64 + r) * 384 + h * 32 + d;
                *(uint32_t*)(ohi + off) = hi;
                *(uint32_t*)(olo + off) = lo;
            }
}

// ---------------- LayerNorm + residual: warp per token -----------------------
__global__ __launch_bounds__(256)
void ln_res_kernel(const float* __restrict__ y, const float* __restrict__ xin,
                   const float* __restrict__ g, const float* __restrict__ bta,
                   float* __restrict__ out, __half* __restrict__ ohi,
                   __half* __restrict__ olo, int mode) {
    const int warp = threadIdx.x >> 5, lane = threadIdx.x & 31;
    const int tok = blockIdx.x * 8 + warp;
    const float* yrow;
    if (mode) {
        int b = tok >> 12, pos = tok & 4095;
        int hc = pos >> 6, wc = pos & 63;
        int hs = (hc + 60) & 63, ws = (wc + 60) & 63;
        int r = (b << 12) + (((hs >> 3) * 8 + (ws >> 3)) << 6) + ((hs & 7) << 3) + (ws & 7);
        yrow = y + (size_t)r * 384;
    } else {
        yrow = y + (size_t)tok * 384;
    }
    float4 v[3];
#pragma unroll
    for (int sgm = 0; sgm < 3; sgm++)
        v[sgm] = *(const float4*)(yrow + (lane + 32 * sgm) * 4);

    float sum = 0.f;
#pragma unroll
    for (int sgm = 0; sgm < 3; sgm++) sum += v[sgm].x + v[sgm].y + v[sgm].z + v[sgm].w;
#pragma unroll
    for (int o2 = 16; o2 > 0; o2 >>= 1) sum += __shfl_xor_sync(0xffffffffu, sum, o2);
    float mu = sum * (1.0f / 384.0f);

    float sq = 0.f;
#pragma unroll
    for (int sgm = 0; sgm < 3; sgm++) {
        v[sgm].x -= mu; v[sgm].y -= mu; v[sgm].z -= mu; v[sgm].w -= mu;
        sq += v[sgm].x * v[sgm].x + v[sgm].y * v[sgm].y +
              v[sgm].z * v[sgm].z + v[sgm].w * v[sgm].w;
    }
#pragma unroll
    for (int o2 = 16; o2 > 0; o2 >>= 1) sq += __shfl_xor_sync(0xffffffffu, sq, o2);
    float inv = rsqrtf(sq * (1.0f / 384.0f) + 1e-6f);

    size_t o_ = (size_t)tok * 384;
#pragma unroll
    for (int sgm = 0; sgm < 3; sgm++) {
        int c = (lane + 32 * sgm) * 4;
        float4 xv = *(const float4*)(xin + o_ + c);
        float4 gv = *(const float4*)(g + c);
        float4 bv = *(const float4*)(bta + c);
        float4 ov;
        ov.x = xv.x + v[sgm].x * inv * gv.x + bv.x;
        ov.y = xv.y + v[sgm].y * inv * gv.y + bv.y;
        ov.z = xv.z + v[sgm].z * inv * gv.z + bv.z;
        ov.w = xv.w + v[sgm].w * inv * gv.w + bv.w;
        *(float4*)(out + o_ + c) = ov;
        if (ohi) {
            uint2 hp, lp;
            hp.x = packsplit_h(ov.x, ov.y, lp.x);
            hp.y = packsplit_h(ov.z, ov.w, lp.y);
            *(uint2*)(ohi + o_ + c) = hp;
            *(uint2*)(olo + o_ + c) = lp;
        }
    }
}

// ---------------- launch ----------------------------------------------------
#define GEMM_SMEM3 (2 * 4 * 128 * 80)    // 81920 (K=32, RS=80)
#define GEMM_SMEM2 (2 * 3 * 128 * 144)   // 110592 (K=64, RS=144)

extern "C" void kernel_launch(void* const* d_in, const int* in_sizes, int n_in,
                              void* d_out, int out_size) {
    const float* x        = (const float*)d_in[0];
    const float* qkv_w    = (const float*)d_in[1];
    const float* q_bias   = (const float*)d_in[2];
    const float* v_bias   = (const float*)d_in[3];
    const float* logit_sc = (const float*)d_in[4];
    const float* cpb_w1   = (const float*)d_in[5];
    const float* cpb_b1   = (const float*)d_in[6];
    const float* cpb_w2   = (const float*)d_in[7];
    const float* proj_w   = (const float*)d_in[8];
    const float* proj_b   = (const float*)d_in[9];
    const float* n1s      = (const float*)d_in[10];
    const float* n1b      = (const float*)d_in[11];
    const float* fc1_w    = (const float*)d_in[12];
    const float* fc1_b    = (const float*)d_in[13];
    const float* fc2_w    = (const float*)d_in[14];
    const float* fc2_b    = (const float*)d_in[15];
    const float* n2s      = (const float*)d_in[16];
    const float* n2b      = (const float*)d_in[17];
    float* out = (float*)d_out;

    float *qkv, *y, *x1, *tab;
    __half *ahi, *alo, *bhi, *blo, *whi, *wlo;
    cudaGetSymbolAddress((void**)&qkv, g_qkv);
    cudaGetSymbolAddress((void**)&y, g_y);
    cudaGetSymbolAddress((void**)&x1, g_x1);
    cudaGetSymbolAddress((void**)&tab, g_tab);
    cudaGetSymbolAddress((void**)&ahi, g_ahi);
    cudaGetSymbolAddress((void**)&alo, g_alo);
    cudaGetSymbolAddress((void**)&bhi, g_bhi);
    cudaGetSymbolAddress((void**)&blo, g_blo);
    cudaGetSymbolAddress((void**)&whi, g_whi);
    cudaGetSymbolAddress((void**)&wlo, g_wlo);

    cudaFuncSetAttribute(gemm_mma<1, 3>, cudaFuncAttributeMaxDynamicSharedMemorySize, GEMM_SMEM3);
    cudaFuncSetAttribute(gemm_mma<2, 2>, cudaFuncAttributeMaxDynamicSharedMemorySize, GEMM_SMEM2);
    cudaFuncSetAttribute(gemm_mma<3, 2>, cudaFuncAttributeMaxDynamicSharedMemorySize, GEMM_SMEM2);

    wprep_kernel<<<(442368 + 255) / 256, 256>>>(qkv_w, whi + WOFF_QKV, wlo + WOFF_QKV, 384, 1152);
    xprep_kernel<<<M_TOK * 96 / 256, 256>>>(x, ahi, alo);

    // QKV: fp16 3-term (Q/K feed the x10 logit-scale amplification)
    gemm_mma<1, 3><<<dim3(9, 1024), 256, GEMM_SMEM3>>>(ahi, alo, whi + WOFF_QKV, wlo + WOFF_QKV,
                                                       qkv, q_bias, v_bias, nullptr, nullptr,
                                                       1152, 384, 0);

    wprep_kernel<<<(147456 + 255) / 256, 256>>>(proj_w, whi + WOFF_PROJ, wlo + WOFF_PROJ, 384, 384);
    wprep_kernel<<<(589824 + 255) / 256, 256>>>(fc1_w, whi + WOFF_FC1, wlo + WOFF_FC1, 384, 1536);
    wprep_kernel<<<(589824 + 255) / 256, 256>>>(fc2_w, whi + WOFF_FC2, wlo + WOFF_FC2, 1536, 384);
    cpb_kernel<<<1, 256>>>(cpb_w1, cpb_b1, cpb_w2, tab);

    attn_kernel<<<2048 * 12, 64>>>(qkv, ahi, alo, tab, logit_sc);

    // proj / fc1 / fc2: fp16 2-term, K=64 chunks (half the sync boundaries)
    gemm_mma<3, 2><<<dim3(3, 1024), 256, GEMM_SMEM2>>>(ahi, alo, whi + WOFF_PROJ, wlo + WOFF_PROJ,
                                                       y, proj_b, nullptr, nullptr, nullptr,
                                                       384, 384, 0);

    ln_res_kernel<<<M_TOK / 8, 256>>>(y, x, n1s, n1b, x1, bhi, blo, 1);

    gemm_mma<2, 2><<<dim3(12, 1024), 256, GEMM_SMEM2>>>(bhi, blo, whi + WOFF_FC1, wlo + WOFF_FC1,
                                                        nullptr, fc1_b, nullptr, ahi, alo,
                                                        1536, 384, 0);

    gemm_mma<3, 2><<<dim3(3, 1024), 256, GEMM_SMEM2>>>(ahi, alo, whi + WOFF_FC2, wlo + WOFF_FC2,
                                                       y, fc2_b, nullptr, nullptr, nullptr,
                                                       384, 1536, 0);

    ln_res_kernel<<<M_TOK / 8, 256>>>(y, x1, n2s, n2b, out, nullptr, nullptr, 0);
}

// round 16
// speedup vs baseline: 1.7971x; 1.2694x over previous
#include <cuda_runtime.h>
#include <cuda_bf16.h>
#include <cuda_fp16.h>
#include <math.h>
#include <stdint.h>

// ---------------- problem constants -----------------------------------------
#define M_TOK 131072
#define C_DIM 384
#define HID_DIM 1536

// ---------------- scratch ----------------------------------------------------
__device__ float g_qkv[(size_t)M_TOK * 1152];
__device__ float g_y[(size_t)M_TOK * 384];
__device__ float g_x1[(size_t)M_TOK * 384];
__device__ __half g_ahi[(size_t)M_TOK * 1536];
__device__ __half g_alo[(size_t)M_TOK * 1536];
__device__ __half g_bhi[(size_t)M_TOK * 384];
__device__ __half g_whi[1769472];
__device__ __half g_wlo[1769472];
__device__ float g_tab[225 * 12];

#define WOFF_QKV 0
#define WOFF_PROJ 442368
#define WOFF_FC1 589824
#define WOFF_FC2 1179648

// ---------------- helpers -----------------------------------------------------
__device__ __forceinline__ uint32_t smem_u32(const void* p) {
    return (uint32_t)__cvta_generic_to_shared(p);
}

__device__ __forceinline__ void cp16(uint32_t dst, const void* src) {
    asm volatile("cp.async.cg.shared.global [%0], [%1], 16;" :: "r"(dst), "l"(src) : "memory");
}
#define CP_COMMIT() asm volatile("cp.async.commit_group;" ::: "memory")
#define CP_WAIT1() asm volatile("cp.async.wait_group 1;" ::: "memory")

__device__ __forceinline__ void mma_f16(float* d, const uint32_t* a, const uint32_t* b) {
    asm volatile(
        "mma.sync.aligned.m16n8k16.row.col.f32.f16.f16.f32 "
        "{%0,%1,%2,%3}, {%4,%5,%6,%7}, {%8,%9}, {%0,%1,%2,%3};"
        : "+f"(d[0]), "+f"(d[1]), "+f"(d[2]), "+f"(d[3])
        : "r"(a[0]), "r"(a[1]), "r"(a[2]), "r"(a[3]), "r"(b[0]), "r"(b[1]));
}

__device__ __forceinline__ void mma_bf16(float* d, const uint32_t* a, const uint32_t* b) {
    asm volatile(
        "mma.sync.aligned.m16n8k16.row.col.f32.bf16.bf16.f32 "
        "{%0,%1,%2,%3}, {%4,%5,%6,%7}, {%8,%9}, {%0,%1,%2,%3};"
        : "+f"(d[0]), "+f"(d[1]), "+f"(d[2]), "+f"(d[3])
        : "r"(a[0]), "r"(a[1]), "r"(a[2]), "r"(a[3]), "r"(b[0]), "r"(b[1]));
}

__device__ __forceinline__ void split2b(float v, __nv_bfloat16& h, __nv_bfloat16& l) {
    h = __float2bfloat16(v);
    l = __float2bfloat16(v - __bfloat162float(h));
}
__device__ __forceinline__ uint32_t packsplit_b(float v0, float v1, uint32_t& lo) {
    __nv_bfloat16 h0, l0, h1, l1;
    split2b(v0, h0, l0);
    split2b(v1, h1, l1);
    __nv_bfloat162 hh = {h0, h1}, ll = {l0, l1};
    lo = *(uint32_t*)&ll;
    return *(uint32_t*)&hh;
}

__device__ __forceinline__ void split2h(float v, __half& h, __half& l) {
    h = __float2half(v);
    l = __float2half(v - __half2float(h));
}
__device__ __forceinline__ uint32_t packsplit_h(float v0, float v1, uint32_t& lo) {
    __half h0, l0, h1, l1;
    split2h(v0, h0, l0);
    split2h(v1, h1, l1);
    __half2 hh = {h0, h1}, ll = {l0, l1};
    lo = *(uint32_t*)&ll;
    return *(uint32_t*)&hh;
}
__device__ __forceinline__ uint32_t pack_h(float v0, float v1) {
    __half2 hh = {__float2half(v0), __float2half(v1)};
    return *(uint32_t*)&hh;
}

__device__ __forceinline__ float fast_tanh(float z) {
    return 1.0f - 2.0f / (__expf(2.0f * z) + 1.0f);
}

// ---------------- index maps ------------------------------------------------
__device__ __forceinline__ int qkv_src_row(int r) {
    int b = r >> 12;
    int t = r & 4095;
    int win = t >> 6, p = t & 63;
    int wh = win >> 3, ww = win & 7;
    int i = p >> 3, j = p & 7;
    int h = (wh * 8 + i + 4) & 63;
    int w = (ww * 8 + j + 4) & 63;
    return (b << 12) + (h << 6) + w;
}

__device__ __forceinline__ int shift_label(int hs, int ws) {
    return ((hs < 56) ? 0 : ((hs < 60) ? 1 : 2)) * 3 +
           ((ws < 56) ? 0 : ((ws < 60) ? 1 : 2));
}

// ---------------- CPB table kernel ------------------------------------------
__device__ __forceinline__ float cpb_coord(int v) {
    float x = (float)v * (8.0f / 7.0f);
    float s = (x > 0.f) ? 1.f : ((x < 0.f) ? -1.f : 0.f);
    return s * log2f(fabsf(x) + 1.0f) * (1.0f / 3.0f);
}

__global__ void cpb_kernel(const float* __restrict__ w1, const float* __restrict__ b1,
                           const float* __restrict__ w2, float* __restrict__ tab) {
    int e = blockIdx.x * blockDim.x + threadIdx.x;
    if (e >= 225) return;
    int a = e / 15, b = e % 15;
    float in0 = cpb_coord(b - 7);
    float in1 = cpb_coord(a - 7);
    float out[12];
#pragma unroll
    for (int hh = 0; hh < 12; hh++) out[hh] = 0.f;
    for (int c = 0; c < 512; c++) {
        float hc = fmaf(in0, w1[c], fmaf(in1, w1[512 + c], b1[c]));
        hc = fmaxf(hc, 0.f);
#pragma unroll
        for (int hh = 0; hh < 12; hh++) out[hh] = fmaf(hc, w2[c * 12 + hh], out[hh]);
    }
#pragma unroll
    for (int hh = 0; hh < 12; hh++)
        tab[e * 12 + hh] = 16.0f / (1.0f + expf(-out[hh]));
}

// ---------------- weight prep ------------------------------------------------
__global__ void wprep_kernel(const float* __restrict__ W, __half* __restrict__ hi,
                             __half* __restrict__ lo, int K, int N) {
    int u = blockIdx.x * 256 + threadIdx.x;
    if (u >= K * N) return;
    int n = u / K, k = u % K;
    float v = W[(size_t)k * N + n];
    __half h, l;
    split2h(v, h, l);
    hi[u] = h;
    if (lo) lo[u] = l;
}

// ---------------- x gather + split -------------------------------------------
__global__ void xprep_kernel(const float* __restrict__ x, __half* __restrict__ hi,
                             __half* __restrict__ lo) {
    int u = blockIdx.x * 256 + threadIdx.x;
    int row = u / 96;
    int c4 = u % 96;
    int src = qkv_src_row(row);
    float4 v = *(const float4*)(x + (size_t)src * 384 + c4 * 4);
    uint2 hp, lp;
    hp.x = packsplit_h(v.x, v.y, lp.x);
    hp.y = packsplit_h(v.z, v.w, lp.y);
    *(uint2*)(hi + (size_t)row * 384 + c4 * 4) = hp;
    *(uint2*)(lo + (size_t)row * 384 + c4 * 4) = lp;
}

// ---------------- mma.sync fp16 GEMM -----------------------------------------
// TERMS=3 (QKV): D = AhBh + AhBl + AlBh; K=32, RS=80, 4 smem matrices.
// TERMS=1 (proj/fc1/fc2): D = AhBh (plain fp16); K=64, RS=144, 2 matrices.
// 128x128 CTA tile, 64x32 warp tiles, 2 CTAs/SM (R11 proven optimum).
template <int EPI, int TERMS>
__global__ __launch_bounds__(256, 2)
void gemm_mma(const __half* __restrict__ Ahi, const __half* __restrict__ Alo,
              const __half* __restrict__ Bhi, const __half* __restrict__ Blo,
              float* __restrict__ C, const float* __restrict__ b0, const float* __restrict__ b1,
              __half* __restrict__ Ohi, __half* __restrict__ Olo,
              int Nn, int Kk, int col0) {
    constexpr int NMAT = (TERMS == 3) ? 4 : 2;
    constexpr int KC = (TERMS == 3) ? 32 : 64;
    constexpr int RSv = (TERMS == 3) ? 80 : 144;
    constexpr int MB = 128 * RSv;
    constexpr int STB = NMAT * MB;
    constexpr int CPR = KC / 8;
    constexpr int UNITS = NMAT * 128 * CPR;
    extern __shared__ char smem[];
    const int t = threadIdx.x;
    const int bm = blockIdx.y, bn = blockIdx.x;
    const int wid = t >> 5, lane = t & 31;
    const int lr = lane >> 2, lc2 = (lane & 3) << 1;
    const int m0 = (wid >> 2) * 64, n0 = (wid & 3) * 32;

    float acc[4][4][4];
#pragma unroll
    for (int i = 0; i < 4; i++)
#pragma unroll
        for (int j = 0; j < 4; j++)
#pragma unroll
            for (int r = 0; r < 4; r++) acc[i][j][r] = 0.f;

    const uint32_t sb0 = smem_u32(smem);

    auto load_stage = [&](int stage, int kb) {
#pragma unroll
        for (int i = 0; i < UNITS / 256; i++) {
            int u = t + i * 256;
            int mat = u / (128 * CPR);
            int rem = u % (128 * CPR);
            int r = rem / CPR, c = rem % CPR;
            const __half* base;
            int rowb;
            if (TERMS == 3) {
                base = (mat == 0) ? Ahi : ((mat == 1) ? Alo : ((mat == 2) ? Bhi : Blo));
                rowb = (mat < 2) ? bm : bn;
            } else {
                base = (mat == 0) ? Ahi : Bhi;
                rowb = (mat == 0) ? bm : bn;
            }
            const __half* src = base + (size_t)(rowb * 128 + r) * Kk + kb + c * 8;
            uint32_t dst = sb0 + stage * STB + mat * MB + r * RSv + c * 16;
            cp16(dst, src);
        }
        CP_COMMIT();
    };

    const int nch = Kk / KC;
    load_stage(0, 0);

    for (int c = 0; c < nch; c++) {
        if (c + 1 < nch) load_stage((c + 1) & 1, (c + 1) * KC);
        else CP_COMMIT();
        CP_WAIT1();
        __syncthreads();

        const char* sb = smem + (c & 1) * STB;
        const char* pAh = sb;
        const char* pAl = sb + MB;                               // TERMS==3 only
        const char* pBh = sb + ((TERMS == 3) ? 2 : 1) * MB;
        const char* pBl = sb + 3 * MB;                           // TERMS==3 only
        const int aoff = (m0 + lr) * RSv + lc2 * 2;
        const int boff = (n0 + lr) * RSv + lc2 * 2;

#pragma unroll
        for (int ks = 0; ks < KC / 16; ks++) {
            const int ko = ks * 32;
            uint32_t bh[4][2];
#pragma unroll
            for (int nt = 0; nt < 4; nt++) {
                int o = boff + nt * 8 * RSv + ko;
                bh[nt][0] = *(const uint32_t*)(pBh + o);
                bh[nt][1] = *(const uint32_t*)(pBh + o + 16);
            }
            uint32_t af[4][4];
#pragma unroll
            for (int mt = 0; mt < 4; mt++) {
                int o = aoff + mt * 16 * RSv + ko;
                af[mt][0] = *(const uint32_t*)(pAh + o);
                af[mt][1] = *(const uint32_t*)(pAh + o + 8 * RSv);
                af[mt][2] = *(const uint32_t*)(pAh + o + 16);
                af[mt][3] = *(const uint32_t*)(pAh + o + 8 * RSv + 16);
            }
#pragma unroll
            for (int mt = 0; mt < 4; mt++)
#pragma unroll
                for (int nt = 0; nt < 4; nt++) mma_f16(acc[mt][nt], af[mt], bh[nt]);
            if (TERMS == 3) {
                uint32_t bl[4][2];
#pragma unroll
                for (int nt = 0; nt < 4; nt++) {
                    int o = boff + nt * 8 * RSv + ko;
                    bl[nt][0] = *(const uint32_t*)(pBl + o);
                    bl[nt][1] = *(const uint32_t*)(pBl + o + 16);
                }
#pragma unroll
                for (int mt = 0; mt < 4; mt++)
#pragma unroll
                    for (int nt = 0; nt < 4; nt++) mma_f16(acc[mt][nt], af[mt], bl[nt]);
#pragma unroll
                for (int mt = 0; mt < 4; mt++) {
                    int o = aoff + mt * 16 * RSv + ko;
                    af[mt][0] = *(const uint32_t*)(pAl + o);
                    af[mt][1] = *(const uint32_t*)(pAl + o + 8 * RSv);
                    af[mt][2] = *(const uint32_t*)(pAl + o + 16);
                    af[mt][3] = *(const uint32_t*)(pAl + o + 8 * RSv + 16);
                }
#pragma unroll
                for (int mt = 0; mt < 4; mt++)
#pragma unroll
                    for (int nt = 0; nt < 4; nt++) mma_f16(acc[mt][nt], af[mt], bh[nt]);
            }
        }
        __syncthreads();
    }

#pragma unroll
    for (int mt = 0; mt < 4; mt++) {
        int rbase = bm * 128 + m0 + mt * 16 + lr;
#pragma unroll
        for (int nt = 0; nt < 4; nt++) {
            int col = col0 + bn * 128 + n0 + nt * 8 + lc2;
#pragma unroll
            for (int half = 0; half < 2; half++) {
                int row = rbase + half * 8;
                float v0 = acc[mt][nt][half * 2 + 0];
                float v1 = acc[mt][nt][half * 2 + 1];
                if (EPI == 1) {
                    v0 += (col < 384) ? b0[col] : ((col < 768) ? 0.f : b1[col - 768]);
                    int c1 = col + 1;
                    v1 += (c1 < 384) ? b0[c1] : ((c1 < 768) ? 0.f : b1[c1 - 768]);
                    float2 o = {v0, v1};
                    *(float2*)(C + (size_t)row * Nn + col) = o;
                } else if (EPI == 3) {
                    v0 += b0[col];
                    v1 += b0[col + 1];
                    float2 o = {v0, v1};
                    *(float2*)(C + (size_t)row * Nn + col) = o;
                } else {
                    v0 += b0[col];
                    v1 += b0[col + 1];
                    float u0 = v0, u1 = v1;
                    v0 = 0.5f * u0 * (1.0f + fast_tanh(0.7978845608028654f *
                                                       (u0 + 0.044715f * u0 * u0 * u0)));
                    v1 = 0.5f * u1 * (1.0f + fast_tanh(0.7978845608028654f *
                                                       (u1 + 0.044715f * u1 * u1 * u1)));
                    *(uint32_t*)(Ohi + (size_t)row * Nn + col) = pack_h(v0, v1);
                }
            }
        }
    }
}

// ---------------- attention on tensor cores (R10 proven; fp16-hi output) -----
__global__ __launch_bounds__(64)
void attn_kernel(const float* __restrict__ qkv, __half* __restrict__ ohi,
                 const float* __restrict__ tab, const float* __restrict__ logit_scale) {
    const int blk = blockIdx.x;
    const int h = blk % 12;
    const int win = blk / 12;
    const int widx = win & 63;
    const int wh8 = (widx >> 3) * 8;
    const int ww8 = (widx & 7) * 8;
    const int t = threadIdx.x;
    const int w = t >> 5, lane = t & 31;
    const int lr = lane >> 2, lq = lane & 3;

    __shared__ __nv_bfloat16 qh[64][40], qlo[64][40];
    __shared__ __nv_bfloat16 kh[64][40], klo[64][40];
    __shared__ __nv_bfloat16 vh[32][72], vlo[32][72];
    __shared__ float tabh[225];

    for (int e = t; e < 225; e += 64) tabh[e] = tab[e * 12 + h];

    {
        const float* qp = qkv + (size_t)(win * 64 + t) * 1152 + h * 32;
        float q[32], k[32], v[32];
#pragma unroll
        for (int i = 0; i < 8; i++) *(float4*)(q + 4 * i) = *(const float4*)(qp + 4 * i);
#pragma unroll
        for (int i = 0; i < 8; i++) *(float4*)(k + 4 * i) = *(const float4*)(qp + 384 + 4 * i);
#pragma unroll
        for (int i = 0; i < 8; i++) *(float4*)(v + 4 * i) = *(const float4*)(qp + 768 + 4 * i);
        float nq = 0.f, nk = 0.f;
#pragma unroll
        for (int d = 0; d < 32; d++) { nq = fmaf(q[d], q[d], nq); nk = fmaf(k[d], k[d], nk); }
        float scale = expf(fminf(logit_scale[h], 4.605170185988091f));
        float rq = rsqrtf(nq) * scale;
        float rk = rsqrtf(nk);
#pragma unroll
        for (int d = 0; d < 32; d += 2) {
            uint32_t lo;
            uint32_t hi = packsplit_b(q[d] * rq, q[d + 1] * rq, lo);
            *(uint32_t*)&qh[t][d] = hi;
            *(uint32_t*)&qlo[t][d] = lo;
            hi = packsplit_b(k[d] * rk, k[d + 1] * rk, lo);
            *(uint32_t*)&kh[t][d] = hi;
            *(uint32_t*)&klo[t][d] = lo;
        }
#pragma unroll
        for (int d = 0; d < 32; d++) {
            __nv_bfloat16 hh, ll;
            split2b(v[d], hh, ll);
            vh[d][t] = hh;
            vlo[d][t] = ll;
        }
    }
    __syncthreads();

    float s[2][8][4];
#pragma unroll
    for (int mt = 0; mt < 2; mt++)
#pragma unroll
        for (int nt = 0; nt < 8; nt++)
#pragma unroll
            for (int e = 0; e < 4; e++) s[mt][nt][e] = 0.f;

#pragma unroll
    for (int pass = 0; pass < 3; pass++) {
        const char* pQ = (pass == 2) ? (const char*)qlo : (const char*)qh;
        const char* pK = (pass == 1) ? (const char*)klo : (const char*)kh;
#pragma unroll
        for (int ks = 0; ks < 2; ks++) {
            const int ko = lq * 4 + ks * 32;
            uint32_t a[2][4];
#pragma unroll
            for (int mt = 0; mt < 2; mt++) {
                int o = (32 * w + 16 * mt + lr) * 80 + ko;
                a[mt][0] = *(const uint32_t*)(pQ + o);
                a[mt][1] = *(const uint32_t*)(pQ + o + 8 * 80);
                a[mt][2] = *(const uint32_t*)(pQ + o + 16);
                a[mt][3] = *(const uint32_t*)(pQ + o + 8 * 80 + 16);
            }
#pragma unroll
            for (int nt = 0; nt < 8; nt++) {
                int o = (nt * 8 + lr) * 80 + ko;
                uint32_t b[2];
                b[0] = *(const uint32_t*)(pK + o);
                b[1] = *(const uint32_t*)(pK + o + 16);
#pragma unroll
                for (int mt = 0; mt < 2; mt++) mma_bf16(s[mt][nt], a[mt], b);
            }
        }
    }

#pragma unroll
    for (int mt = 0; mt < 2; mt++) {
#pragma unroll
        for (int half = 0; half < 2; half++) {
            const int r = 32 * w + 16 * mt + 8 * half + lr;
            const int ti = r >> 3, tj = r & 7;
            const int labt = shift_label(wh8 + ti, ww8 + tj);
            float mx = -1e30f;
#pragma unroll
            for (int nt = 0; nt < 8; nt++) {
#pragma unroll
                for (int e2 = 0; e2 < 2; e2++) {
                    int u = nt * 8 + lq * 2 + e2;
                    int ui = u >> 3, uj = u & 7;
                    float val = s[mt][nt][half * 2 + e2] +
                                tabh[(tj - uj + 7) * 15 + (ti - ui + 7)];
                    if (shift_label(wh8 + ui, ww8 + uj) != labt) val -= 100.0f;
                    s[mt][nt][half * 2 + e2] = val;
                    mx = fmaxf(mx, val);
                }
            }
            mx = fmaxf(mx, __shfl_xor_sync(0xffffffffu, mx, 1));
            mx = fmaxf(mx, __shfl_xor_sync(0xffffffffu, mx, 2));
            float ss = 0.f;
#pragma unroll
            for (int nt = 0; nt < 8; nt++) {
#pragma unroll
                for (int e2 = 0; e2 < 2; e2++) {
                    float e = __expf(s[mt][nt][half * 2 + e2] - mx);
                    s[mt][nt][half * 2 + e2] = e;
                    ss += e;
                }
            }
            ss += __shfl_xor_sync(0xffffffffu, ss, 1);
            ss += __shfl_xor_sync(0xffffffffu, ss, 2);
            float inv = 1.0f / ss;
#pragma unroll
            for (int nt = 0; nt < 8; nt++) {
#pragma unroll
                for (int e2 = 0; e2 < 2; e2++)
                    s[mt][nt][half * 2 + e2] *= inv;
            }
        }
    }

    uint32_t ph[2][4][4], pl[2][4][4];
#pragma unroll
    for (int mt = 0; mt < 2; mt++)
#pragma unroll
        for (int kb = 0; kb < 4; kb++)
#pragma unroll
            for (int j = 0; j < 4; j++) {
                int nt = 2 * kb + (j >> 1);
                int base = (j & 1) * 2;
                ph[mt][kb][j] = packsplit_b(s[mt][nt][base], s[mt][nt][base + 1],
                                            pl[mt][kb][j]);
            }

    float o[2][4][4];
#pragma unroll
    for (int mt = 0; mt < 2; mt++)
#pragma unroll
        for (int nt = 0; nt < 4; nt++)
#pragma unroll
            for (int e = 0; e < 4; e++) o[mt][nt][e] = 0.f;

#pragma unroll
    for (int pass = 0; pass < 3; pass++) {
        const uint32_t (*pa)[4][4] = (pass == 2) ? pl : ph;
        const char* pV = (pass == 1) ? (const char*)vlo : (const char*)vh;
#pragma unroll
        for (int kb = 0; kb < 4; kb++) {
#pragma unroll
            for (int nt = 0; nt < 4; nt++) {
                int off = (nt * 8 + lr) * 144 + lq * 4 + kb * 32;
                uint32_t b[2];
                b[0] = *(const uint32_t*)(pV + off);
                b[1] = *(const uint32_t*)(pV + off + 16);
#pragma unroll
                for (int mt = 0; mt < 2; mt++) mma_bf16(o[mt][nt], pa[mt][kb], b);
            }
        }
    }

#pragma unroll
    for (int mt = 0; mt < 2; mt++)
#pragma unroll
        for (int nt = 0; nt < 4; nt++)
#pragma unroll
            for (int half = 0; half < 2; half++) {
                int r = 32 * w + 16 * mt + 8 * half + lr;
                int d = nt * 8 + lq * 2;
                size_t off = (size_t)(win * 64 + r) * 384 + h * 32 + d;
                *(uint32_t*)(ohi + off) = pack_h(o[mt][nt][half * 2],
                                                 o[mt][nt][half * 2 + 1]);
            }
}

// ---------------- LayerNorm + residual: warp per token -----------------------
__global__ __launch_bounds__(256)
void ln_res_kernel(const float* __restrict__ y, const float* __restrict__ xin,
                   const float* __restrict__ g, const float* __restrict__ bta,
                   float* __restrict__ out, __half* __restrict__ ohi, int mode) {
    const int warp = threadIdx.x >> 5, lane = threadIdx.x & 31;
    const int tok = blockIdx.x * 8 + warp;
    const float* yrow;
    if (mode) {
        int b = tok >> 12, pos = tok & 4095;
        int hc = pos >> 6, wc = pos & 63;
        int hs = (hc + 60) & 63, ws = (wc + 60) & 63;
        int r = (b << 12) + (((hs >> 3) * 8 + (ws >> 3)) << 6) + ((hs & 7) << 3) + (ws & 7);
        yrow = y + (size_t)r * 384;
    } else {
        yrow = y + (size_t)tok * 384;
    }
    float4 v[3];
#pragma unroll
    for (int sgm = 0; sgm < 3; sgm++)
        v[sgm] = *(const float4*)(yrow + (lane + 32 * sgm) * 4);

    float sum = 0.f;
#pragma unroll
    for (int sgm = 0; sgm < 3; sgm++) sum += v[sgm].x + v[sgm].y + v[sgm].z + v[sgm].w;
#pragma unroll
    for (int o2 = 16; o2 > 0; o2 >>= 1) sum += __shfl_xor_sync(0xffffffffu, sum, o2);
    float mu = sum * (1.0f / 384.0f);

    float sq = 0.f;
#pragma unroll
    for (int sgm = 0; sgm < 3; sgm++) {
        v[sgm].x -= mu; v[sgm].y -= mu; v[sgm].z -= mu; v[sgm].w -= mu;
        sq += v[sgm].x * v[sgm].x + v[sgm].y * v[sgm].y +
              v[sgm].z * v[sgm].z + v[sgm].w * v[sgm].w;
    }
#pragma unroll
    for (int o2 = 16; o2 > 0; o2 >>= 1) sq += __shfl_xor_sync(0xffffffffu, sq, o2);
    float inv = rsqrtf(sq * (1.0f / 384.0f) + 1e-6f);

    size_t o_ = (size_t)tok * 384;
#pragma unroll
    for (int sgm = 0; sgm < 3; sgm++) {
        int c = (lane + 32 * sgm) * 4;
        float4 xv = *(const float4*)(xin + o_ + c);
        float4 gv = *(const float4*)(g + c);
        float4 bv = *(const float4*)(bta + c);
        float4 ov;
        ov.x = xv.x + v[sgm].x * inv * gv.x + bv.x;
        ov.y = xv.y + v[sgm].y * inv * gv.y + bv.y;
        ov.z = xv.z + v[sgm].z * inv * gv.z + bv.z;
        ov.w = xv.w + v[sgm].w * inv * gv.w + bv.w;
        *(float4*)(out + o_ + c) = ov;
        if (ohi) {
            uint2 hp;
            hp.x = pack_h(ov.x, ov.y);
            hp.y = pack_h(ov.z, ov.w);
            *(uint2*)(ohi + o_ + c) = hp;
        }
    }
}

// ---------------- launch ----------------------------------------------------
#define GEMM_SMEM3 (2 * 4 * 128 * 80)    // 81920 (K=32, RS=80, 4 mats)
#define GEMM_SMEM1 (2 * 2 * 128 * 144)   // 73728 (K=64, RS=144, 2 mats)

extern "C" void kernel_launch(void* const* d_in, const int* in_sizes, int n_in,
                              void* d_out, int out_size) {
    const float* x        = (const float*)d_in[0];
    const float* qkv_w    = (const float*)d_in[1];
    const float* q_bias   = (const float*)d_in[2];
    const float* v_bias   = (const float*)d_in[3];
    const float* logit_sc = (const float*)d_in[4];
    const float* cpb_w1   = (const float*)d_in[5];
    const float* cpb_b1   = (const float*)d_in[6];
    const float* cpb_w2   = (const float*)d_in[7];
    const float* proj_w   = (const float*)d_in[8];
    const float* proj_b   = (const float*)d_in[9];
    const float* n1s      = (const float*)d_in[10];
    const float* n1b      = (const float*)d_in[11];
    const float* fc1_w    = (const float*)d_in[12];
    const float* fc1_b    = (const float*)d_in[13];
    const float* fc2_w    = (const float*)d_in[14];
    const float* fc2_b    = (const float*)d_in[15];
    const float* n2s      = (const float*)d_in[16];
    const float* n2b      = (const float*)d_in[17];
    float* out = (float*)d_out;

    float *qkv, *y, *x1, *tab;
    __half *ahi, *alo, *bhi, *whi, *wlo;
    cudaGetSymbolAddress((void**)&qkv, g_qkv);
    cudaGetSymbolAddress((void**)&y, g_y);
    cudaGetSymbolAddress((void**)&x1, g_x1);
    cudaGetSymbolAddress((void**)&tab, g_tab);
    cudaGetSymbolAddress((void**)&ahi, g_ahi);
    cudaGetSymbolAddress((void**)&alo, g_alo);
    cudaGetSymbolAddress((void**)&bhi, g_bhi);
    cudaGetSymbolAddress((void**)&whi, g_whi);
    cudaGetSymbolAddress((void**)&wlo, g_wlo);

    cudaFuncSetAttribute(gemm_mma<1, 3>, cudaFuncAttributeMaxDynamicSharedMemorySize, GEMM_SMEM3);
    cudaFuncSetAttribute(gemm_mma<2, 1>, cudaFuncAttributeMaxDynamicSharedMemorySize, GEMM_SMEM1);
    cudaFuncSetAttribute(gemm_mma<3, 1>, cudaFuncAttributeMaxDynamicSharedMemorySize, GEMM_SMEM1);

    wprep_kernel<<<(442368 + 255) / 256, 256>>>(qkv_w, whi + WOFF_QKV, wlo + WOFF_QKV, 384, 1152);
    xprep_kernel<<<M_TOK * 96 / 256, 256>>>(x, ahi, alo);

    // QKV: fp16 3-term (Q/K feed the x10 logit-scale amplification)
    gemm_mma<1, 3><<<dim3(9, 1024), 256, GEMM_SMEM3>>>(ahi, alo, whi + WOFF_QKV, wlo + WOFF_QKV,
                                                       qkv, q_bias, v_bias, nullptr, nullptr,
                                                       1152, 384, 0);

    // weight hi-only preps for 1-term GEMMs
    wprep_kernel<<<(147456 + 255) / 256, 256>>>(proj_w, whi + WOFF_PROJ, nullptr, 384, 384);
    wprep_kernel<<<(589824 + 255) / 256, 256>>>(fc1_w, whi + WOFF_FC1, nullptr, 384, 1536);
    wprep_kernel<<<(589824 + 255) / 256, 256>>>(fc2_w, whi + WOFF_FC2, nullptr, 1536, 384);
    cpb_kernel<<<1, 256>>>(cpb_w1, cpb_b1, cpb_w2, tab);

    attn_kernel<<<2048 * 12, 64>>>(qkv, ahi, tab, logit_sc);

    // proj / fc1 / fc2: plain fp16 1-term
    gemm_mma<3, 1><<<dim3(3, 1024), 256, GEMM_SMEM1>>>(ahi, nullptr, whi + WOFF_PROJ, nullptr,
                                                       y, proj_b, nullptr, nullptr, nullptr,
                                                       384, 384, 0);

    ln_res_kernel<<<M_TOK / 8, 256>>>(y, x, n1s, n1b, x1, bhi, 1);

    gemm_mma<2, 1><<<dim3(12, 1024), 256, GEMM_SMEM1>>>(bhi, nullptr, whi + WOFF_FC1, nullptr,
                                                        nullptr, fc1_b, nullptr, ahi, nullptr,
                                                        1536, 384, 0);

    gemm_mma<3, 1><<<dim3(3, 1024), 256, GEMM_SMEM1>>>(ahi, nullptr, whi + WOFF_FC2, nullptr,
                                                       y, fc2_b, nullptr, nullptr, nullptr,
                                                       384, 1536, 0);

    ln_res_kernel<<<M_TOK / 8, 256>>>(y, x1, n2s, n2b, out, nullptr, 0);
}

// round 17
// speedup vs baseline: 1.9031x; 1.0589x over previous
#include <cuda_runtime.h>
#include <cuda_bf16.h>
#include <cuda_fp16.h>
#include <math.h>
#include <stdint.h>

// ---------------- problem constants -----------------------------------------
#define M_TOK 131072
#define C_DIM 384
#define HID_DIM 1536

// ---------------- scratch ----------------------------------------------------
__device__ float g_qkv[(size_t)M_TOK * 1152];
__device__ float g_y[(size_t)M_TOK * 384];
__device__ float g_x1[(size_t)M_TOK * 384];
__device__ __half g_ahi[(size_t)M_TOK * 1536];
__device__ __half g_alo[(size_t)M_TOK * 1536];
__device__ __half g_bhi[(size_t)M_TOK * 384];
__device__ __half g_whi[1769472];
__device__ __half g_wlo[1769472];
__device__ float g_tab[225 * 12];

#define WOFF_QKV 0
#define WOFF_PROJ 442368
#define WOFF_FC1 589824
#define WOFF_FC2 1179648

// ---------------- helpers -----------------------------------------------------
__device__ __forceinline__ uint32_t smem_u32(const void* p) {
    return (uint32_t)__cvta_generic_to_shared(p);
}

__device__ __forceinline__ void cp16(uint32_t dst, const void* src) {
    asm volatile("cp.async.cg.shared.global [%0], [%1], 16;" :: "r"(dst), "l"(src) : "memory");
}
#define CP_COMMIT() asm volatile("cp.async.commit_group;" ::: "memory")
#define CP_WAIT1() asm volatile("cp.async.wait_group 1;" ::: "memory")

__device__ __forceinline__ void mma_f16(float* d, const uint32_t* a, const uint32_t* b) {
    asm volatile(
        "mma.sync.aligned.m16n8k16.row.col.f32.f16.f16.f32 "
        "{%0,%1,%2,%3}, {%4,%5,%6,%7}, {%8,%9}, {%0,%1,%2,%3};"
        : "+f"(d[0]), "+f"(d[1]), "+f"(d[2]), "+f"(d[3])
        : "r"(a[0]), "r"(a[1]), "r"(a[2]), "r"(a[3]), "r"(b[0]), "r"(b[1]));
}

__device__ __forceinline__ void mma_bf16(float* d, const uint32_t* a, const uint32_t* b) {
    asm volatile(
        "mma.sync.aligned.m16n8k16.row.col.f32.bf16.bf16.f32 "
        "{%0,%1,%2,%3}, {%4,%5,%6,%7}, {%8,%9}, {%0,%1,%2,%3};"
        : "+f"(d[0]), "+f"(d[1]), "+f"(d[2]), "+f"(d[3])
        : "r"(a[0]), "r"(a[1]), "r"(a[2]), "r"(a[3]), "r"(b[0]), "r"(b[1]));
}

__device__ __forceinline__ void split2b(float v, __nv_bfloat16& h, __nv_bfloat16& l) {
    h = __float2bfloat16(v);
    l = __float2bfloat16(v - __bfloat162float(h));
}
__device__ __forceinline__ uint32_t packsplit_b(float v0, float v1, uint32_t& lo) {
    __nv_bfloat16 h0, l0, h1, l1;
    split2b(v0, h0, l0);
    split2b(v1, h1, l1);
    __nv_bfloat162 hh = {h0, h1}, ll = {l0, l1};
    lo = *(uint32_t*)&ll;
    return *(uint32_t*)&hh;
}

__device__ __forceinline__ void split2h(float v, __half& h, __half& l) {
    h = __float2half(v);
    l = __float2half(v - __half2float(h));
}
__device__ __forceinline__ uint32_t packsplit_h(float v0, float v1, uint32_t& lo) {
    __half h0, l0, h1, l1;
    split2h(v0, h0, l0);
    split2h(v1, h1, l1);
    __half2 hh = {h0, h1}, ll = {l0, l1};
    lo = *(uint32_t*)&ll;
    return *(uint32_t*)&hh;
}
__device__ __forceinline__ uint32_t pack_h(float v0, float v1) {
    __half2 hh = {__float2half(v0), __float2half(v1)};
    return *(uint32_t*)&hh;
}

__device__ __forceinline__ float fast_tanh(float z) {
    return 1.0f - 2.0f / (__expf(2.0f * z) + 1.0f);
}

// ---------------- index maps ------------------------------------------------
__device__ __forceinline__ int qkv_src_row(int r) {
    int b = r >> 12;
    int t = r & 4095;
    int win = t >> 6, p = t & 63;
    int wh = win >> 3, ww = win & 7;
    int i = p >> 3, j = p & 7;
    int h = (wh * 8 + i + 4) & 63;
    int w = (ww * 8 + j + 4) & 63;
    return (b << 12) + (h << 6) + w;
}

__device__ __forceinline__ int shift_label(int hs, int ws) {
    return ((hs < 56) ? 0 : ((hs < 60) ? 1 : 2)) * 3 +
           ((ws < 56) ? 0 : ((ws < 60) ? 1 : 2));
}

// ---------------- CPB table kernel ------------------------------------------
__device__ __forceinline__ float cpb_coord(int v) {
    float x = (float)v * (8.0f / 7.0f);
    float s = (x > 0.f) ? 1.f : ((x < 0.f) ? -1.f : 0.f);
    return s * log2f(fabsf(x) + 1.0f) * (1.0f / 3.0f);
}

__global__ void cpb_kernel(const float* __restrict__ w1, const float* __restrict__ b1,
                           const float* __restrict__ w2, float* __restrict__ tab) {
    int e = blockIdx.x * blockDim.x + threadIdx.x;
    if (e >= 225) return;
    int a = e / 15, b = e % 15;
    float in0 = cpb_coord(b - 7);
    float in1 = cpb_coord(a - 7);
    float out[12];
#pragma unroll
    for (int hh = 0; hh < 12; hh++) out[hh] = 0.f;
    for (int c = 0; c < 512; c++) {
        float hc = fmaf(in0, w1[c], fmaf(in1, w1[512 + c], b1[c]));
        hc = fmaxf(hc, 0.f);
#pragma unroll
        for (int hh = 0; hh < 12; hh++) out[hh] = fmaf(hc, w2[c * 12 + hh], out[hh]);
    }
#pragma unroll
    for (int hh = 0; hh < 12; hh++)
        tab[e * 12 + hh] = 16.0f / (1.0f + expf(-out[hh]));
}

// ---------------- weight prep ------------------------------------------------
__global__ void wprep_kernel(const float* __restrict__ W, __half* __restrict__ hi,
                             __half* __restrict__ lo, int K, int N) {
    int u = blockIdx.x * 256 + threadIdx.x;
    if (u >= K * N) return;
    int n = u / K, k = u % K;
    float v = W[(size_t)k * N + n];
    __half h, l;
    split2h(v, h, l);
    hi[u] = h;
    if (lo) lo[u] = l;
}

// ---------------- x gather + split -------------------------------------------
__global__ void xprep_kernel(const float* __restrict__ x, __half* __restrict__ hi,
                             __half* __restrict__ lo) {
    int u = blockIdx.x * 256 + threadIdx.x;
    int row = u / 96;
    int c4 = u % 96;
    int src = qkv_src_row(row);
    float4 v = *(const float4*)(x + (size_t)src * 384 + c4 * 4);
    uint2 hp, lp;
    hp.x = packsplit_h(v.x, v.y, lp.x);
    hp.y = packsplit_h(v.z, v.w, lp.y);
    *(uint2*)(hi + (size_t)row * 384 + c4 * 4) = hp;
    *(uint2*)(lo + (size_t)row * 384 + c4 * 4) = lp;
}

// ---------------- mma.sync fp16 GEMM -----------------------------------------
// TERMS=3: D = AhBh + AhBl + AlBh; K=32, RS=80, 4 smem matrices. (Q/K path)
// TERMS=1: D = AhBh (plain fp16); K=64, RS=144, 2 matrices. (V/proj/fc1/fc2)
// 128x128 CTA tile, 64x32 warp tiles, 2 CTAs/SM (R11 proven optimum).
template <int EPI, int TERMS>
__global__ __launch_bounds__(256, 2)
void gemm_mma(const __half* __restrict__ Ahi, const __half* __restrict__ Alo,
              const __half* __restrict__ Bhi, const __half* __restrict__ Blo,
              float* __restrict__ C, const float* __restrict__ b0, const float* __restrict__ b1,
              __half* __restrict__ Ohi, __half* __restrict__ Olo,
              int Nn, int Kk, int col0) {
    constexpr int NMAT = (TERMS == 3) ? 4 : 2;
    constexpr int KC = (TERMS == 3) ? 32 : 64;
    constexpr int RSv = (TERMS == 3) ? 80 : 144;
    constexpr int MB = 128 * RSv;
    constexpr int STB = NMAT * MB;
    constexpr int CPR = KC / 8;
    constexpr int UNITS = NMAT * 128 * CPR;
    extern __shared__ char smem[];
    const int t = threadIdx.x;
    const int bm = blockIdx.y, bn = blockIdx.x;
    const int wid = t >> 5, lane = t & 31;
    const int lr = lane >> 2, lc2 = (lane & 3) << 1;
    const int m0 = (wid >> 2) * 64, n0 = (wid & 3) * 32;

    float acc[4][4][4];
#pragma unroll
    for (int i = 0; i < 4; i++)
#pragma unroll
        for (int j = 0; j < 4; j++)
#pragma unroll
            for (int r = 0; r < 4; r++) acc[i][j][r] = 0.f;

    const uint32_t sb0 = smem_u32(smem);

    auto load_stage = [&](int stage, int kb) {
#pragma unroll
        for (int i = 0; i < UNITS / 256; i++) {
            int u = t + i * 256;
            int mat = u / (128 * CPR);
            int rem = u % (128 * CPR);
            int r = rem / CPR, c = rem % CPR;
            const __half* base;
            int rowb;
            if (TERMS == 3) {
                base = (mat == 0) ? Ahi : ((mat == 1) ? Alo : ((mat == 2) ? Bhi : Blo));
                rowb = (mat < 2) ? bm : bn;
            } else {
                base = (mat == 0) ? Ahi : Bhi;
                rowb = (mat == 0) ? bm : bn;
            }
            const __half* src = base + (size_t)(rowb * 128 + r) * Kk + kb + c * 8;
            uint32_t dst = sb0 + stage * STB + mat * MB + r * RSv + c * 16;
            cp16(dst, src);
        }
        CP_COMMIT();
    };

    const int nch = Kk / KC;
    load_stage(0, 0);

    for (int c = 0; c < nch; c++) {
        if (c + 1 < nch) load_stage((c + 1) & 1, (c + 1) * KC);
        else CP_COMMIT();
        CP_WAIT1();
        __syncthreads();

        const char* sb = smem + (c & 1) * STB;
        const char* pAh = sb;
        const char* pAl = sb + MB;
        const char* pBh = sb + ((TERMS == 3) ? 2 : 1) * MB;
        const char* pBl = sb + 3 * MB;
        const int aoff = (m0 + lr) * RSv + lc2 * 2;
        const int boff = (n0 + lr) * RSv + lc2 * 2;

#pragma unroll
        for (int ks = 0; ks < KC / 16; ks++) {
            const int ko = ks * 32;
            uint32_t bh[4][2];
#pragma unroll
            for (int nt = 0; nt < 4; nt++) {
                int o = boff + nt * 8 * RSv + ko;
                bh[nt][0] = *(const uint32_t*)(pBh + o);
                bh[nt][1] = *(const uint32_t*)(pBh + o + 16);
            }
            uint32_t af[4][4];
#pragma unroll
            for (int mt = 0; mt < 4; mt++) {
                int o = aoff + mt * 16 * RSv + ko;
                af[mt][0] = *(const uint32_t*)(pAh + o);
                af[mt][1] = *(const uint32_t*)(pAh + o + 8 * RSv);
                af[mt][2] = *(const uint32_t*)(pAh + o + 16);
                af[mt][3] = *(const uint32_t*)(pAh + o + 8 * RSv + 16);
            }
#pragma unroll
            for (int mt = 0; mt < 4; mt++)
#pragma unroll
                for (int nt = 0; nt < 4; nt++) mma_f16(acc[mt][nt], af[mt], bh[nt]);
            if (TERMS == 3) {
                uint32_t bl[4][2];
#pragma unroll
                for (int nt = 0; nt < 4; nt++) {
                    int o = boff + nt * 8 * RSv + ko;
                    bl[nt][0] = *(const uint32_t*)(pBl + o);
                    bl[nt][1] = *(const uint32_t*)(pBl + o + 16);
                }
#pragma unroll
                for (int mt = 0; mt < 4; mt++)
#pragma unroll
                    for (int nt = 0; nt < 4; nt++) mma_f16(acc[mt][nt], af[mt], bl[nt]);
#pragma unroll
                for (int mt = 0; mt < 4; mt++) {
                    int o = aoff + mt * 16 * RSv + ko;
                    af[mt][0] = *(const uint32_t*)(pAl + o);
                    af[mt][1] = *(const uint32_t*)(pAl + o + 8 * RSv);
                    af[mt][2] = *(const uint32_t*)(pAl + o + 16);
                    af[mt][3] = *(const uint32_t*)(pAl + o + 8 * RSv + 16);
                }
#pragma unroll
                for (int mt = 0; mt < 4; mt++)
#pragma unroll
                    for (int nt = 0; nt < 4; nt++) mma_f16(acc[mt][nt], af[mt], bh[nt]);
            }
        }
        __syncthreads();
    }

#pragma unroll
    for (int mt = 0; mt < 4; mt++) {
        int rbase = bm * 128 + m0 + mt * 16 + lr;
#pragma unroll
        for (int nt = 0; nt < 4; nt++) {
            int col = col0 + bn * 128 + n0 + nt * 8 + lc2;
#pragma unroll
            for (int half = 0; half < 2; half++) {
                int row = rbase + half * 8;
                float v0 = acc[mt][nt][half * 2 + 0];
                float v1 = acc[mt][nt][half * 2 + 1];
                if (EPI == 1) {
                    v0 += (col < 384) ? b0[col] : ((col < 768) ? 0.f : b1[col - 768]);
                    int c1 = col + 1;
                    v1 += (c1 < 384) ? b0[c1] : ((c1 < 768) ? 0.f : b1[c1 - 768]);
                    float2 o = {v0, v1};
                    *(float2*)(C + (size_t)row * Nn + col) = o;
                } else if (EPI == 3) {
                    v0 += b0[col];
                    v1 += b0[col + 1];
                    float2 o = {v0, v1};
                    *(float2*)(C + (size_t)row * Nn + col) = o;
                } else {
                    v0 += b0[col];
                    v1 += b0[col + 1];
                    float u0 = v0, u1 = v1;
                    v0 = 0.5f * u0 * (1.0f + fast_tanh(0.7978845608028654f *
                                                       (u0 + 0.044715f * u0 * u0 * u0)));
                    v1 = 0.5f * u1 * (1.0f + fast_tanh(0.7978845608028654f *
                                                       (u1 + 0.044715f * u1 * u1 * u1)));
                    *(uint32_t*)(Ohi + (size_t)row * Nn + col) = pack_h(v0, v1);
                }
            }
        }
    }
}

// ---------------- attention on tensor cores (R10 proven; fp16-hi output) -----
__global__ __launch_bounds__(64)
void attn_kernel(const float* __restrict__ qkv, __half* __restrict__ ohi,
                 const float* __restrict__ tab, const float* __restrict__ logit_scale) {
    const int blk = blockIdx.x;
    const int h = blk % 12;
    const int win = blk / 12;
    const int widx = win & 63;
    const int wh8 = (widx >> 3) * 8;
    const int ww8 = (widx & 7) * 8;
    const int t = threadIdx.x;
    const int w = t >> 5, lane = t & 31;
    const int lr = lane >> 2, lq = lane & 3;

    __shared__ __nv_bfloat16 qh[64][40], qlo[64][40];
    __shared__ __nv_bfloat16 kh[64][40], klo[64][40];
    __shared__ __nv_bfloat16 vh[32][72], vlo[32][72];
    __shared__ float tabh[225];

    for (int e = t; e < 225; e += 64) tabh[e] = tab[e * 12 + h];

    {
        const float* qp = qkv + (size_t)(win * 64 + t) * 1152 + h * 32;
        float q[32], k[32], v[32];
#pragma unroll
        for (int i = 0; i < 8; i++) *(float4*)(q + 4 * i) = *(const float4*)(qp + 4 * i);
#pragma unroll
        for (int i = 0; i < 8; i++) *(float4*)(k + 4 * i) = *(const float4*)(qp + 384 + 4 * i);
#pragma unroll
        for (int i = 0; i < 8; i++) *(float4*)(v + 4 * i) = *(const float4*)(qp + 768 + 4 * i);
        float nq = 0.f, nk = 0.f;
#pragma unroll
        for (int d = 0; d < 32; d++) { nq = fmaf(q[d], q[d], nq); nk = fmaf(k[d], k[d], nk); }
        float scale = expf(fminf(logit_scale[h], 4.605170185988091f));
        float rq = rsqrtf(nq) * scale;
        float rk = rsqrtf(nk);
#pragma unroll
        for (int d = 0; d < 32; d += 2) {
            uint32_t lo;
            uint32_t hi = packsplit_b(q[d] * rq, q[d + 1] * rq, lo);
            *(uint32_t*)&qh[t][d] = hi;
            *(uint32_t*)&qlo[t][d] = lo;
            hi = packsplit_b(k[d] * rk, k[d + 1] * rk, lo);
            *(uint32_t*)&kh[t][d] = hi;
            *(uint32_t*)&klo[t][d] = lo;
        }
#pragma unroll
        for (int d = 0; d < 32; d++) {
            __nv_bfloat16 hh, ll;
            split2b(v[d], hh, ll);
            vh[d][t] = hh;
            vlo[d][t] = ll;
        }
    }
    __syncthreads();

    float s[2][8][4];
#pragma unroll
    for (int mt = 0; mt < 2; mt++)
#pragma unroll
        for (int nt = 0; nt < 8; nt++)
#pragma unroll
            for (int e = 0; e < 4; e++) s[mt][nt][e] = 0.f;

#pragma unroll
    for (int pass = 0; pass < 3; pass++) {
        const char* pQ = (pass == 2) ? (const char*)qlo : (const char*)qh;
        const char* pK = (pass == 1) ? (const char*)klo : (const char*)kh;
#pragma unroll
        for (int ks = 0; ks < 2; ks++) {
            const int ko = lq * 4 + ks * 32;
            uint32_t a[2][4];
#pragma unroll
            for (int mt = 0; mt < 2; mt++) {
                int o = (32 * w + 16 * mt + lr) * 80 + ko;
                a[mt][0] = *(const uint32_t*)(pQ + o);
                a[mt][1] = *(const uint32_t*)(pQ + o + 8 * 80);
                a[mt][2] = *(const uint32_t*)(pQ + o + 16);
                a[mt][3] = *(const uint32_t*)(pQ + o + 8 * 80 + 16);
            }
#pragma unroll
            for (int nt = 0; nt < 8; nt++) {
                int o = (nt * 8 + lr) * 80 + ko;
                uint32_t b[2];
                b[0] = *(const uint32_t*)(pK + o);
                b[1] = *(const uint32_t*)(pK + o + 16);
#pragma unroll
                for (int mt = 0; mt < 2; mt++) mma_bf16(s[mt][nt], a[mt], b);
            }
        }
    }

#pragma unroll
    for (int mt = 0; mt < 2; mt++) {
#pragma unroll
        for (int half = 0; half < 2; half++) {
            const int r = 32 * w + 16 * mt + 8 * half + lr;
            const int ti = r >> 3, tj = r & 7;
            const int labt = shift_label(wh8 + ti, ww8 + tj);
            float mx = -1e30f;
#pragma unroll
            for (int nt = 0; nt < 8; nt++) {
#pragma unroll
                for (int e2 = 0; e2 < 2; e2++) {
                    int u = nt * 8 + lq * 2 + e2;
                    int ui = u >> 3, uj = u & 7;
                    float val = s[mt][nt][half * 2 + e2] +
                                tabh[(tj - uj + 7) * 15 + (ti - ui + 7)];
                    if (shift_label(wh8 + ui, ww8 + uj) != labt) val -= 100.0f;
                    s[mt][nt][half * 2 + e2] = val;
                    mx = fmaxf(mx, val);
                }
            }
            mx = fmaxf(mx, __shfl_xor_sync(0xffffffffu, mx, 1));
            mx = fmaxf(mx, __shfl_xor_sync(0xffffffffu, mx, 2));
            float ss = 0.f;
#pragma unroll
            for (int nt = 0; nt < 8; nt++) {
#pragma unroll
                for (int e2 = 0; e2 < 2; e2++) {
                    float e = __expf(s[mt][nt][half * 2 + e2] - mx);
                    s[mt][nt][half * 2 + e2] = e;
                    ss += e;
                }
            }
            ss += __shfl_xor_sync(0xffffffffu, ss, 1);
            ss += __shfl_xor_sync(0xffffffffu, ss, 2);
            float inv = 1.0f / ss;
#pragma unroll
            for (int nt = 0; nt < 8; nt++) {
#pragma unroll
                for (int e2 = 0; e2 < 2; e2++)
                    s[mt][nt][half * 2 + e2] *= inv;
            }
        }
    }

    uint32_t ph[2][4][4], pl[2][4][4];
#pragma unroll
    for (int mt = 0; mt < 2; mt++)
#pragma unroll
        for (int kb = 0; kb < 4; kb++)
#pragma unroll
            for (int j = 0; j < 4; j++) {
                int nt = 2 * kb + (j >> 1);
                int base = (j & 1) * 2;
                ph[mt][kb][j] = packsplit_b(s[mt][nt][base], s[mt][nt][base + 1],
                                            pl[mt][kb][j]);
            }

    float o[2][4][4];
#pragma unroll
    for (int mt = 0; mt < 2; mt++)
#pragma unroll
        for (int nt = 0; nt < 4; nt++)
#pragma unroll
            for (int e = 0; e < 4; e++) o[mt][nt][e] = 0.f;

#pragma unroll
    for (int pass = 0; pass < 3; pass++) {
        const uint32_t (*pa)[4][4] = (pass == 2) ? pl : ph;
        const char* pV = (pass == 1) ? (const char*)vlo : (const char*)vh;
#pragma unroll
        for (int kb = 0; kb < 4; kb++) {
#pragma unroll
            for (int nt = 0; nt < 4; nt++) {
                int off = (nt * 8 + lr) * 144 + lq * 4 + kb * 32;
                uint32_t b[2];
                b[0] = *(const uint32_t*)(pV + off);
                b[1] = *(const uint32_t*)(pV + off + 16);
#pragma unroll
                for (int mt = 0; mt < 2; mt++) mma_bf16(o[mt][nt], pa[mt][kb], b);
            }
        }
    }

#pragma unroll
    for (int mt = 0; mt < 2; mt++)
#pragma unroll
        for (int nt = 0; nt < 4; nt++)
#pragma unroll
            for (int half = 0; half < 2; half++) {
                int r = 32 * w + 16 * mt + 8 * half + lr;
                int d = nt * 8 + lq * 2;
                size_t off = (size_t)(win * 64 + r) * 384 + h * 32 + d;
                *(uint32_t*)(ohi + off) = pack_h(o[mt][nt][half * 2],
                                                 o[mt][nt][half * 2 + 1]);
            }
}

// ---------------- LayerNorm + residual: warp per token -----------------------
__global__ __launch_bounds__(256)
void ln_res_kernel(const float* __restrict__ y, const float* __restrict__ xin,
                   const float* __restrict__ g, const float* __restrict__ bta,
                   float* __restrict__ out, __half* __restrict__ ohi, int mode) {
    const int warp = threadIdx.x >> 5, lane = threadIdx.x & 31;
    const int tok = blockIdx.x * 8 + warp;
    const float* yrow;
    if (mode) {
        int b = tok >> 12, pos = tok & 4095;
        int hc = pos >> 6, wc = pos & 63;
        int hs = (hc + 60) & 63, ws = (wc + 60) & 63;
        int r = (b << 12) + (((hs >> 3) * 8 + (ws >> 3)) << 6) + ((hs & 7) << 3) + (ws & 7);
        yrow = y + (size_t)r * 384;
    } else {
        yrow = y + (size_t)tok * 384;
    }
    float4 v[3];
#pragma unroll
    for (int sgm = 0; sgm < 3; sgm++)
        v[sgm] = *(const float4*)(yrow + (lane + 32 * sgm) * 4);

    float sum = 0.f;
#pragma unroll
    for (int sgm = 0; sgm < 3; sgm++) sum += v[sgm].x + v[sgm].y + v[sgm].z + v[sgm].w;
#pragma unroll
    for (int o2 = 16; o2 > 0; o2 >>= 1) sum += __shfl_xor_sync(0xffffffffu, sum, o2);
    float mu = sum * (1.0f / 384.0f);

    float sq = 0.f;
#pragma unroll
    for (int sgm = 0; sgm < 3; sgm++) {
        v[sgm].x -= mu; v[sgm].y -= mu; v[sgm].z -= mu; v[sgm].w -= mu;
        sq += v[sgm].x * v[sgm].x + v[sgm].y * v[sgm].y +
              v[sgm].z * v[sgm].z + v[sgm].w * v[sgm].w;
    }
#pragma unroll
    for (int o2 = 16; o2 > 0; o2 >>= 1) sq += __shfl_xor_sync(0xffffffffu, sq, o2);
    float inv = rsqrtf(sq * (1.0f / 384.0f) + 1e-6f);

    size_t o_ = (size_t)tok * 384;
#pragma unroll
    for (int sgm = 0; sgm < 3; sgm++) {
        int c = (lane + 32 * sgm) * 4;
        float4 xv = *(const float4*)(xin + o_ + c);
        float4 gv = *(const float4*)(g + c);
        float4 bv = *(const float4*)(bta + c);
        float4 ov;
        ov.x = xv.x + v[sgm].x * inv * gv.x + bv.x;
        ov.y = xv.y + v[sgm].y * inv * gv.y + bv.y;
        ov.z = xv.z + v[sgm].z * inv * gv.z + bv.z;
        ov.w = xv.w + v[sgm].w * inv * gv.w + bv.w;
        *(float4*)(out + o_ + c) = ov;
        if (ohi) {
            uint2 hp;
            hp.x = pack_h(ov.x, ov.y);
            hp.y = pack_h(ov.z, ov.w);
            *(uint2*)(ohi + o_ + c) = hp;
        }
    }
}

// ---------------- launch ----------------------------------------------------
#define GEMM_SMEM3 (2 * 4 * 128 * 80)    // 81920 (K=32, RS=80, 4 mats)
#define GEMM_SMEM1 (2 * 2 * 128 * 144)   // 73728 (K=64, RS=144, 2 mats)

extern "C" void kernel_launch(void* const* d_in, const int* in_sizes, int n_in,
                              void* d_out, int out_size) {
    const float* x        = (const float*)d_in[0];
    const float* qkv_w    = (const float*)d_in[1];
    const float* q_bias   = (const float*)d_in[2];
    const float* v_bias   = (const float*)d_in[3];
    const float* logit_sc = (const float*)d_in[4];
    const float* cpb_w1   = (const float*)d_in[5];
    const float* cpb_b1   = (const float*)d_in[6];
    const float* cpb_w2   = (const float*)d_in[7];
    const float* proj_w   = (const float*)d_in[8];
    const float* proj_b   = (const float*)d_in[9];
    const float* n1s      = (const float*)d_in[10];
    const float* n1b      = (const float*)d_in[11];
    const float* fc1_w    = (const float*)d_in[12];
    const float* fc1_b    = (const float*)d_in[13];
    const float* fc2_w    = (const float*)d_in[14];
    const float* fc2_b    = (const float*)d_in[15];
    const float* n2s      = (const float*)d_in[16];
    const float* n2b      = (const float*)d_in[17];
    float* out = (float*)d_out;

    float *qkv, *y, *x1, *tab;
    __half *ahi, *alo, *bhi, *whi, *wlo;
    cudaGetSymbolAddress((void**)&qkv, g_qkv);
    cudaGetSymbolAddress((void**)&y, g_y);
    cudaGetSymbolAddress((void**)&x1, g_x1);
    cudaGetSymbolAddress((void**)&tab, g_tab);
    cudaGetSymbolAddress((void**)&ahi, g_ahi);
    cudaGetSymbolAddress((void**)&alo, g_alo);
    cudaGetSymbolAddress((void**)&bhi, g_bhi);
    cudaGetSymbolAddress((void**)&whi, g_whi);
    cudaGetSymbolAddress((void**)&wlo, g_wlo);

    cudaFuncSetAttribute(gemm_mma<1, 3>, cudaFuncAttributeMaxDynamicSharedMemorySize, GEMM_SMEM3);
    cudaFuncSetAttribute(gemm_mma<1, 1>, cudaFuncAttributeMaxDynamicSharedMemorySize, GEMM_SMEM1);
    cudaFuncSetAttribute(gemm_mma<2, 1>, cudaFuncAttributeMaxDynamicSharedMemorySize, GEMM_SMEM1);
    cudaFuncSetAttribute(gemm_mma<3, 1>, cudaFuncAttributeMaxDynamicSharedMemorySize, GEMM_SMEM1);

    wprep_kernel<<<(442368 + 255) / 256, 256>>>(qkv_w, whi + WOFF_QKV, wlo + WOFF_QKV, 384, 1152);
    xprep_kernel<<<M_TOK * 96 / 256, 256>>>(x, ahi, alo);

    // Q/K part (cols 0-767): fp16 3-term (x10 logit-scale amplification path)
    gemm_mma<1, 3><<<dim3(6, 1024), 256, GEMM_SMEM3>>>(ahi, alo, whi + WOFF_QKV, wlo + WOFF_QKV,
                                                       qkv, q_bias, v_bias, nullptr, nullptr,
                                                       1152, 384, 0);
    // V part (cols 768-1151): plain fp16 1-term (no amplification)
    gemm_mma<1, 1><<<dim3(3, 1024), 256, GEMM_SMEM1>>>(ahi, nullptr,
                                                       whi + WOFF_QKV + (size_t)768 * 384, nullptr,
                                                       qkv, q_bias, v_bias, nullptr, nullptr,
                                                       1152, 384, 768);

    wprep_kernel<<<(147456 + 255) / 256, 256>>>(proj_w, whi + WOFF_PROJ, nullptr, 384, 384);
    wprep_kernel<<<(589824 + 255) / 256, 256>>>(fc1_w, whi + WOFF_FC1, nullptr, 384, 1536);
    wprep_kernel<<<(589824 + 255) / 256, 256>>>(fc2_w, whi + WOFF_FC2, nullptr, 1536, 384);
    cpb_kernel<<<1, 256>>>(cpb_w1, cpb_b1, cpb_w2, tab);

    attn_kernel<<<2048 * 12, 64>>>(qkv, ahi, tab, logit_sc);

    gemm_mma<3, 1><<<dim3(3, 1024), 256, GEMM_SMEM1>>>(ahi, nullptr, whi + WOFF_PROJ, nullptr,
                                                       y, proj_b, nullptr, nullptr, nullptr,
                                                       384, 384, 0);

    ln_res_kernel<<<M_TOK / 8, 256>>>(y, x, n1s, n1b, x1, bhi, 1);

    gemm_mma<2, 1><<<dim3(12, 1024), 256, GEMM_SMEM1>>>(bhi, nullptr, whi + WOFF_FC1, nullptr,
                                                        nullptr, fc1_b, nullptr, ahi, nullptr,
                                                        1536, 384, 0);

    gemm_mma<3, 1><<<dim3(3, 1024), 256, GEMM_SMEM1>>>(ahi, nullptr, whi + WOFF_FC2, nullptr,
                                                       y, fc2_b, nullptr, nullptr, nullptr,
                                                       384, 1536, 0);

    ln_res_kernel<<<M_TOK / 8, 256>>>(y, x1, n2s, n2b, out, nullptr, 0);
}